// round 13
// baseline (speedup 1.0000x reference)
#include <cuda_runtime.h>
#include <cuda_bf16.h>
#include <math.h>
#include <stdint.h>

#define B_ 4
#define T_ 1024
#define DIM_ 512
#define H_ 8
#define DH_ 64
#define FF_ 2048
#define KW 31

typedef __nv_bfloat16 bf16;

// ---------------- scratch (device globals) ------------------------------------
__device__ float g_S  [B_*T_*DIM_];
__device__ float g_T1 [B_*T_*FF_];
__device__ float g_QKV[B_*T_*3*DIM_];
__device__ float g_C1 [B_*T_*DIM_];
__device__ float g_F  [B_*H_*T_];
__device__ float g_TAB[H_*2048];
__device__ double g_PART[B_*128*2];
__device__ float2 g_STATS[B_];
__device__ bf16 g_Shi[B_*T_*DIM_],  g_Slo[B_*T_*DIM_];
__device__ bf16 g_T1hi[B_*T_*FF_],  g_T1lo[B_*T_*FF_];
__device__ bf16 g_Ohi[B_*T_*DIM_],  g_Olo[B_*T_*DIM_];
__device__ bf16 g_N1hi[B_*T_*DIM_], g_N1lo[B_*T_*DIM_];
__device__ bf16 g_Wf1a_hi[FF_*DIM_],  g_Wf1a_lo[FF_*DIM_];
__device__ bf16 g_Wf1b_hi[DIM_*FF_],  g_Wf1b_lo[DIM_*FF_];
__device__ bf16 g_Wqkv_hi[1536*DIM_], g_Wqkv_lo[1536*DIM_];
__device__ bf16 g_Wout_hi[DIM_*DIM_], g_Wout_lo[DIM_*DIM_];
__device__ bf16 g_Wpw1_hi[1024*DIM_], g_Wpw1_lo[1024*DIM_];
__device__ bf16 g_Wpw2_hi[DIM_*DIM_], g_Wpw2_lo[DIM_*DIM_];
__device__ bf16 g_Wf2a_hi[FF_*DIM_],  g_Wf2a_lo[FF_*DIM_];
__device__ bf16 g_Wf2b_hi[DIM_*FF_],  g_Wf2b_lo[DIM_*FF_];

// ---------------- helpers ------------------------------------------------------
__device__ __forceinline__ uint32_t smem_to_u32(const void* p) {
    uint32_t a;
    asm("{ .reg .u64 t; cvta.to.shared.u64 t, %1; cvt.u32.u64 %0, t; }" : "=r"(a) : "l"(p));
    return a;
}
__device__ __forceinline__ void cp16(uint32_t dst, const void* src) {
    asm volatile("cp.async.cg.shared.global [%0], [%1], 16;" :: "r"(dst), "l"(src));
}
#define CP_COMMIT() asm volatile("cp.async.commit_group;" ::: "memory")
#define CP_WAIT1()  asm volatile("cp.async.wait_group 1;" ::: "memory")

__device__ __forceinline__ void ldsm4(uint32_t& r0, uint32_t& r1, uint32_t& r2, uint32_t& r3, uint32_t addr) {
    asm volatile("ldmatrix.sync.aligned.m8n8.x4.shared.b16 {%0,%1,%2,%3}, [%4];"
                 : "=r"(r0), "=r"(r1), "=r"(r2), "=r"(r3) : "r"(addr));
}
__device__ __forceinline__ void mma16816(float* d, const uint32_t* a, uint32_t b0, uint32_t b1) {
    asm volatile("mma.sync.aligned.m16n8k16.row.col.f32.bf16.bf16.f32 "
                 "{%0,%1,%2,%3}, {%4,%5,%6,%7}, {%8,%9}, {%0,%1,%2,%3};"
                 : "+f"(d[0]), "+f"(d[1]), "+f"(d[2]), "+f"(d[3])
                 : "r"(a[0]), "r"(a[1]), "r"(a[2]), "r"(a[3]), "r"(b0), "r"(b1));
}
__device__ __forceinline__ void bf16_split(float v, bf16* hi, bf16* lo, size_t idx) {
    bf16 h = __float2bfloat16(v);
    hi[idx] = h;
    lo[idx] = __float2bfloat16(v - __bfloat162float(h));
}
__device__ __forceinline__ uint32_t packbf(float a, float b) {
    __nv_bfloat162 t = __floats2bfloat162_rn(a, b);
    return *(uint32_t*)&t;
}
__device__ __forceinline__ void bf16_split2(float v0, float v1, bf16* hi, bf16* lo, size_t off) {
    bf16 h0 = __float2bfloat16(v0), h1 = __float2bfloat16(v1);
    *(uint32_t*)(hi + off) = packbf(v0, v1);
    *(uint32_t*)(lo + off) = packbf(v0 - __bfloat162float(h0), v1 - __bfloat162float(h1));
}
__device__ __forceinline__ uint32_t swz(int r, int c) {
    return (uint32_t)(r * 64 + ((c ^ ((r >> 1) & 3)) << 4));
}
#define SWZ128(r, c8) ((uint32_t)((r)*128 + (((c8) ^ ((r)&7)) << 4)))

// ---------------- mma.sync GEMM (BM in {128,64}, BN=128, opt. GN partials) ------
template<int BM>
__device__ __forceinline__ void stage_load2(
    uint32_t stg,
    const bf16* __restrict__ Ahi, const bf16* __restrict__ Alo,
    const bf16* __restrict__ Bhi, const bf16* __restrict__ Blo,
    int m0, int n0, int K, int kc, int tid)
{
    constexpr int ACH = BM * 4;
    constexpr int TC = 2 * ACH + 2 * 512;
    constexpr int ITER = TC / 256;
#pragma unroll
    for (int it = 0; it < ITER; it++) {
        int idx = it * 256 + tid;
        const bf16* base; int r, c; uint32_t moff; int grow;
        if (idx < 2 * ACH) {
            int mat = idx / ACH;
            int e = idx - mat * ACH;
            r = e >> 2; c = e & 3;
            base = mat ? Alo : Ahi;
            grow = m0 + r;
            moff = (uint32_t)mat * (BM * 64);
        } else {
            int e2 = idx - 2 * ACH;
            int mat = e2 >> 9;
            int e = e2 & 511;
            r = e >> 2; c = e & 3;
            base = mat ? Blo : Bhi;
            grow = n0 + r;
            moff = 2 * (BM * 64) + (uint32_t)mat * 8192;
        }
        cp16(stg + moff + swz(r, c), base + (size_t)grow * K + kc * 32 + c * 8);
    }
}

template<int BM, bool GELU, bool RED>
__global__ void __launch_bounds__(256, 2) gemm_mma(
    const bf16* __restrict__ Ahi, const bf16* __restrict__ Alo,
    const bf16* __restrict__ Bhi, const bf16* __restrict__ Blo,
    const float* __restrict__ bias, const float* __restrict__ resid,
    float* __restrict__ C, bf16* __restrict__ Chi, bf16* __restrict__ Clo,
    int M, int N, int K, float alpha)
{
    constexpr int NW_N = (BM == 128) ? 2 : 4;
    constexpr int NT8  = (BM == 128) ? 8 : 4;
    constexpr int NBF  = NT8 / 2;
    constexpr int A_BYTES = BM * 64;
    constexpr int STG = 2 * A_BYTES + 2 * 8192;

    extern __shared__ char sm[];
    float* bias_s = (float*)sm;
    uint32_t tiles = smem_to_u32(sm) + 512;
    int tid = threadIdx.x, wid = tid >> 5, lane = tid & 31;
    int n0 = blockIdx.x * 128, m0 = blockIdx.y * BM;
    int wm = wid / NW_N, wn = wid % NW_N;

    if (tid < 128) bias_s[tid] = bias[n0 + tid];

    float acc[2][NT8][4];
#pragma unroll
    for (int i = 0; i < 2; i++)
#pragma unroll
        for (int j = 0; j < NT8; j++)
#pragma unroll
            for (int q = 0; q < 4; q++) acc[i][j][q] = 0.f;

    const int nk = K >> 5;
    stage_load2<BM>(tiles + 0 * STG, Ahi, Alo, Bhi, Blo, m0, n0, K, 0, tid);
    CP_COMMIT();
    stage_load2<BM>(tiles + 1 * STG, Ahi, Alo, Bhi, Blo, m0, n0, K, 1, tid);
    CP_COMMIT();

    int rowA = wm * 32 + (lane & 15);
    int rowB = wn * (NBF * 16) + (lane & 15);
    int csel = lane >> 4;

    int slot = 0;
    for (int kc = 0; kc < nk; kc++) {
        CP_WAIT1();
        __syncthreads();
        if (kc + 2 < nk) {
            int ns = slot + 2; if (ns >= 3) ns -= 3;
            stage_load2<BM>(tiles + ns * STG, Ahi, Alo, Bhi, Blo, m0, n0, K, kc + 2, tid);
            CP_COMMIT();
        }
        uint32_t stg = tiles + slot * STG;
#pragma unroll
        for (int kk = 0; kk < 2; kk++) {
            int chunk = kk * 2 + csel;
            uint32_t af[2][4], bh[NBF][4], bl[NBF][4];
#pragma unroll
            for (int mt = 0; mt < 2; mt++) {
                int r = rowA + mt * 16;
                ldsm4(af[mt][0], af[mt][1], af[mt][2], af[mt][3], stg + swz(r, chunk));
            }
#pragma unroll
            for (int nt = 0; nt < NBF; nt++) {
                int r = rowB + nt * 16;
                ldsm4(bh[nt][0], bh[nt][1], bh[nt][2], bh[nt][3], stg + 2 * A_BYTES + swz(r, chunk));
                ldsm4(bl[nt][0], bl[nt][1], bl[nt][2], bl[nt][3], stg + 2 * A_BYTES + 8192 + swz(r, chunk));
            }
#pragma unroll
            for (int mt = 0; mt < 2; mt++)
#pragma unroll
                for (int nt8 = 0; nt8 < NT8; nt8++) {
                    int g = nt8 >> 1, s = nt8 & 1;
                    mma16816(acc[mt][nt8], af[mt], bh[g][s], bh[g][s + 2]);
                    mma16816(acc[mt][nt8], af[mt], bl[g][s], bl[g][s + 2]);
                }
#pragma unroll
            for (int mt = 0; mt < 2; mt++) {
                int r = rowA + mt * 16;
                ldsm4(af[mt][0], af[mt][1], af[mt][2], af[mt][3], stg + A_BYTES + swz(r, chunk));
            }
#pragma unroll
            for (int mt = 0; mt < 2; mt++)
#pragma unroll
                for (int nt8 = 0; nt8 < NT8; nt8++) {
                    int g = nt8 >> 1, s = nt8 & 1;
                    mma16816(acc[mt][nt8], af[mt], bh[g][s], bh[g][s + 2]);
                }
        }
        slot++; if (slot >= 3) slot = 0;
    }

    double su = 0.0, sq = 0.0;
    int rm = lane >> 2, cp = (lane & 3) * 2;
#pragma unroll
    for (int mt = 0; mt < 2; mt++) {
#pragma unroll
        for (int half = 0; half < 2; half++) {
            int m = m0 + wm * 32 + mt * 16 + half * 8 + rm;
#pragma unroll
            for (int nt8 = 0; nt8 < NT8; nt8++) {
                int nl = wn * (NT8 * 8) + nt8 * 8 + cp;
                size_t off = (size_t)m * N + n0 + nl;
                float v0 = acc[mt][nt8][half * 2 + 0] + bias_s[nl];
                float v1 = acc[mt][nt8][half * 2 + 1] + bias_s[nl + 1];
                if (GELU) {
                    v0 = 0.5f * v0 * (1.0f + erff(v0 * 0.70710678f));
                    v1 = 0.5f * v1 * (1.0f + erff(v1 * 0.70710678f));
                }
                v0 *= alpha; v1 *= alpha;
                if (resid) {
                    float2 r = *(const float2*)(resid + off);
                    v0 += r.x; v1 += r.y;
                }
                if (C) *(float2*)(C + off) = make_float2(v0, v1);
                if (Chi) bf16_split2(v0, v1, Chi, Clo, off);
                if (RED) {
                    su += (double)v0 + (double)v1;
                    sq += (double)v0 * v0 + (double)v1 * v1;
                }
            }
        }
    }
    if (RED) {
        // tiles region is dead now; reuse as reduction scratch
        __syncthreads();
        double* rs = (double*)(sm + 512);
        rs[tid] = su; rs[256 + tid] = sq;
        __syncthreads();
        for (int st = 128; st > 0; st >>= 1) {
            if (tid < st) {
                rs[tid] += rs[tid + st];
                rs[256 + tid] += rs[256 + tid + st];
            }
            __syncthreads();
        }
        if (tid == 0) {
            int bb = m0 >> 10;                        // batch (BM=64 never crosses)
            int tidx = ((blockIdx.y & 15)) * gridDim.x + blockIdx.x;
            g_PART[(bb * 128 + tidx) * 2 + 0] = rs[0];
            g_PART[(bb * 128 + tidx) * 2 + 1] = rs[256];
        }
    }
}

// ---------------- fused weight split (packed stores) ----------------------------
__device__ void do_split_t(float (*t)[33], const float* __restrict__ W, bf16* hi, bf16* lo,
                           int K, int N, int tile) {
    int kt = K / 32;
    int k0 = (tile % kt) * 32, n0 = (tile / kt) * 32;
    int tx = threadIdx.x & 31, ty = threadIdx.x >> 5;
    for (int r = ty; r < 32; r += 8)
        t[r][tx] = W[(size_t)(k0 + r) * N + n0 + tx];
    __syncthreads();
    int tx2 = threadIdx.x & 15, ty2 = threadIdx.x >> 4;
    for (int rr = ty2; rr < 32; rr += 16)
        bf16_split2(t[2*tx2][rr], t[2*tx2+1][rr], hi, lo, (size_t)(n0 + rr) * K + k0 + 2*tx2);
}
__device__ void do_split_d(const float* __restrict__ W, bf16* hi, bf16* lo, int tile) {
    int i = tile * 1024 + threadIdx.x * 4;
    float4 v = *(const float4*)(W + i);
    bf16_split2(v.x, v.y, hi, lo, i);
    bf16_split2(v.z, v.w, hi, lo, i + 2);
}
__global__ void wsplit_all(const float* ff1_w1, const float* ff1_w2, const float* qkv_w,
                           const float* out_w, const float* pw1_w, const float* pw2_w,
                           const float* ff2_w1, const float* ff2_w2) {
    __shared__ float t[32][33];
    int b = blockIdx.x;
    if      (b < 1024) do_split_t(t, ff1_w1, g_Wf1a_hi, g_Wf1a_lo, DIM_, FF_, b);
    else if (b < 2048) do_split_t(t, ff1_w2, g_Wf1b_hi, g_Wf1b_lo, FF_, DIM_, b - 1024);
    else if (b < 2816) do_split_t(t, qkv_w,  g_Wqkv_hi, g_Wqkv_lo, DIM_, 1536, b - 2048);
    else if (b < 3072) do_split_t(t, out_w,  g_Wout_hi, g_Wout_lo, DIM_, DIM_, b - 2816);
    else if (b < 3584) do_split_d(pw1_w, g_Wpw1_hi, g_Wpw1_lo, b - 3072);
    else if (b < 3840) do_split_d(pw2_w, g_Wpw2_hi, g_Wpw2_lo, b - 3584);
    else if (b < 4864) do_split_t(t, ff2_w1, g_Wf2a_hi, g_Wf2a_lo, DIM_, FF_, b - 3840);
    else               do_split_t(t, ff2_w2, g_Wf2b_hi, g_Wf2b_lo, FF_, DIM_, b - 4864);
}

// ---------------- transposes ---------------------------------------------------
__global__ void transpose_bdt_to_btd(const float* __restrict__ in, float* __restrict__ out,
                                     bf16* __restrict__ ohi, bf16* __restrict__ olo) {
    __shared__ float tile[32][33];
    int b = blockIdx.z;
    int t0 = blockIdx.x * 32, d0 = blockIdx.y * 32;
    for (int i = threadIdx.y; i < 32; i += 8)
        tile[i][threadIdx.x] = in[((size_t)b*DIM_ + d0 + i)*T_ + t0 + threadIdx.x];
    __syncthreads();
    int tid = threadIdx.y * 32 + threadIdx.x;
    int dx = (tid & 15) * 2;
    int r0 = tid >> 4;
#pragma unroll
    for (int rstep = 0; rstep < 2; rstep++) {
        int i = r0 + rstep * 16;
        float v0 = tile[dx][i], v1 = tile[dx + 1][i];
        size_t o = ((size_t)b*T_ + t0 + i)*DIM_ + d0 + dx;
        *(float2*)(out + o) = make_float2(v0, v1);
        bf16_split2(v0, v1, ohi, olo, o);
    }
}
__global__ void transpose_btd_to_bdt(const float* __restrict__ in, float* __restrict__ out) {
    __shared__ float tile[32][33];
    int b = blockIdx.z;
    int d0 = blockIdx.x * 32, t0 = blockIdx.y * 32;
    for (int i = threadIdx.y; i < 32; i += 8)
        tile[i][threadIdx.x] = in[((size_t)b*T_ + t0 + i)*DIM_ + d0 + threadIdx.x];
    __syncthreads();
    for (int i = threadIdx.y; i < 32; i += 8)
        out[((size_t)b*DIM_ + d0 + i)*T_ + t0 + threadIdx.x] = tile[threadIdx.x][i];
}

// ---------------- rel-bias table + gates ----------------------------------------
__global__ void rel_table_kernel(const float* __restrict__ rel_embed, float* __restrict__ tab) {
    int idx = blockIdx.x * 256 + threadIdx.x;
    if (idx >= 2047 * H_) return;
    int rr = idx >> 3, h = idx & 7;
    int rel = rr - 1023;
    int sign = (rel >= 0) ? 1 : 0;
    int ap = rel >= 0 ? rel : -rel;
    int bidx;
    if (ap < 80) bidx = ap;
    else {
        float lr = logf((float)ap / 80.0f) / 2.3025851f;
        int lp = (int)(80.0f + lr * 80.0f);
        bidx = lp < 159 ? lp : 159;
    }
    int bucket = bidx + sign * 160;
    bucket = bucket < 0 ? 0 : (bucket > 319 ? 319 : bucket);
    tab[h * 2048 + rr] = rel_embed[bucket * H_ + h];
}
__global__ void gates_kernel(const float* __restrict__ QKV, const float* __restrict__ gu,
                             const float* __restrict__ gw, const float* __restrict__ sh,
                             float* __restrict__ F) {
    int row = blockIdx.x * 8 + (threadIdx.x >> 5);
    int lane = threadIdx.x & 31;
    int t = row & (T_-1);
    int bh = row >> 10;
    int h = bh & (H_-1), b = bh >> 3;
    const float* q = QKV + ((size_t)(b*T_ + t))*1536 + h*DH_;
    float su = 0.f, sw = 0.f;
    for (int d = lane; d < DH_; d += 32) {
        float qv = q[d];
        su += qv * gu[h*DH_ + d];
        sw += qv * gw[h*DH_ + d];
    }
#pragma unroll
    for (int m = 16; m; m >>= 1) {
        su += __shfl_xor_sync(0xffffffff, su, m);
        sw += __shfl_xor_sync(0xffffffff, sw, m);
    }
    if (lane == 0) {
        float g_u = 1.f / (1.f + expf(-su));
        float g_w = 1.f / (1.f + expf(-sw));
        F[row] = 1.f + g_u + (1.f - g_u) * sh[h] * g_w;
    }
}

// ---------------- flash attention on mma.sync -----------------------------------
#define AQHI 0
#define AQLO 16384
#define AKHI 32768
#define AKLO 40960
#define AVTH 49152
#define AVTL 57344
#define AWOF 65536
#define ATTN_SMEM (65536 + 768)

__global__ void __launch_bounds__(256, 2) attn_mma(
    const float* __restrict__ QKV, const float* __restrict__ F,
    const float* __restrict__ TAB, bf16* __restrict__ Ohi, bf16* __restrict__ Olo)
{
    extern __shared__ char sma[];
    uint32_t sb = smem_to_u32(sma);
    float* Ws = (float*)(sma + AWOF);

    int tid = threadIdx.x, wid = tid >> 5, lane = tid & 31;
    int t0 = blockIdx.x * 128, h = blockIdx.y, b = blockIdx.z;

#pragma unroll
    for (int i = 0; i < 4; i++) {
        int task = i * 256 + tid;
        int r = task >> 3, c8 = task & 7;
        const float* src = QKV + ((size_t)(b*T_ + t0 + r))*1536 + h*64 + c8*8;
        float4 v0 = *(const float4*)src, v1 = *(const float4*)(src + 4);
        float vv[8] = {v0.x, v0.y, v0.z, v0.w, v1.x, v1.y, v1.z, v1.w};
        bf16 h8[8], l8[8];
#pragma unroll
        for (int j = 0; j < 8; j++) {
            h8[j] = __float2bfloat16(vv[j]);
            l8[j] = __float2bfloat16(vv[j] - __bfloat162float(h8[j]));
        }
        uint32_t off = SWZ128(r, c8);
        *(uint4*)(sma + AQHI + off) = *(uint4*)h8;
        *(uint4*)(sma + AQLO + off) = *(uint4*)l8;
    }
    int rloc0 = wid * 16 + (lane >> 2);
    int cbase = (lane & 3) * 2;
    float f0 = F[((b*H_ + h) << 10) + t0 + rloc0];
    float f1 = F[((b*H_ + h) << 10) + t0 + rloc0 + 8];

    float m_run[2] = {-1e30f, -1e30f}, l_run[2] = {0.f, 0.f};
    float acc_o[8][4];
#pragma unroll
    for (int i = 0; i < 8; i++)
#pragma unroll
        for (int q = 0; q < 4; q++) acc_o[i][q] = 0.f;

    for (int st = 0; st < T_/64; st++) {
        int s0 = st * 64;
        __syncthreads();
#pragma unroll
        for (int i = 0; i < 2; i++) {
            int task = i * 256 + tid;
            int r = task >> 3, c8 = task & 7;
            const float* src = QKV + ((size_t)(b*T_ + s0 + r))*1536 + 512 + h*64 + c8*8;
            float4 v0 = *(const float4*)src, v1 = *(const float4*)(src + 4);
            float vv[8] = {v0.x, v0.y, v0.z, v0.w, v1.x, v1.y, v1.z, v1.w};
            bf16 h8[8], l8[8];
#pragma unroll
            for (int j = 0; j < 8; j++) {
                h8[j] = __float2bfloat16(vv[j]);
                l8[j] = __float2bfloat16(vv[j] - __bfloat162float(h8[j]));
            }
            uint32_t off = SWZ128(r, c8);
            *(uint4*)(sma + AKHI + off) = *(uint4*)h8;
            *(uint4*)(sma + AKLO + off) = *(uint4*)l8;
        }
        {
            int sp = (tid & 31) * 2;
            int dg = (tid >> 5) * 8;
            const float* src0 = QKV + ((size_t)(b*T_ + s0 + sp))*1536 + 1024 + h*64 + dg;
            const float* src1 = src0 + 1536;
            float4 a0 = *(const float4*)src0, a1 = *(const float4*)(src0 + 4);
            float4 b0 = *(const float4*)src1, b1 = *(const float4*)(src1 + 4);
            float r0v[8] = {a0.x, a0.y, a0.z, a0.w, a1.x, a1.y, a1.z, a1.w};
            float r1v[8] = {b0.x, b0.y, b0.z, b0.w, b1.x, b1.y, b1.z, b1.w};
#pragma unroll
            for (int j = 0; j < 8; j++) {
                int d = dg + j;
                uint32_t off = (uint32_t)(d*128 + ((((sp >> 3) ^ (d & 7))) << 4) + (sp & 7)*2);
                float v0 = r0v[j], v1 = r1v[j];
                bf16 h0 = __float2bfloat16(v0), h1 = __float2bfloat16(v1);
                *(uint32_t*)(sma + AVTH + off) = packbf(v0, v1);
                *(uint32_t*)(sma + AVTL + off) =
                    packbf(v0 - __bfloat162float(h0), v1 - __bfloat162float(h1));
            }
        }
        if (tid < 192) {
            int gidx = s0 - t0 + 896 + tid;
            gidx = gidx < 0 ? 0 : (gidx > 2046 ? 2046 : gidx);
            Ws[tid] = TAB[h*2048 + gidx];
        }
        __syncthreads();

        float acc_s[8][4];
#pragma unroll
        for (int i = 0; i < 8; i++)
#pragma unroll
            for (int q = 0; q < 4; q++) acc_s[i][q] = 0.f;
        int qr = wid * 16 + (lane & 15);
#pragma unroll
        for (int ks = 0; ks < 4; ks++) {
            int chunk = ks * 2 + (lane >> 4);
            uint32_t qa[4], kh[4][4], kl[4][4];
            ldsm4(qa[0], qa[1], qa[2], qa[3], sb + AQHI + SWZ128(qr, chunk));
#pragma unroll
            for (int nt = 0; nt < 4; nt++) {
                int kr = nt * 16 + (lane & 15);
                ldsm4(kh[nt][0], kh[nt][1], kh[nt][2], kh[nt][3], sb + AKHI + SWZ128(kr, chunk));
                ldsm4(kl[nt][0], kl[nt][1], kl[nt][2], kl[nt][3], sb + AKLO + SWZ128(kr, chunk));
            }
#pragma unroll
            for (int nt8 = 0; nt8 < 8; nt8++) {
                int g = nt8 >> 1, s8 = nt8 & 1;
                mma16816(acc_s[nt8], qa, kh[g][s8], kh[g][s8 + 2]);
                mma16816(acc_s[nt8], qa, kl[g][s8], kl[g][s8 + 2]);
            }
            ldsm4(qa[0], qa[1], qa[2], qa[3], sb + AQLO + SWZ128(qr, chunk));
#pragma unroll
            for (int nt8 = 0; nt8 < 8; nt8++) {
                int g = nt8 >> 1, s8 = nt8 & 1;
                mma16816(acc_s[nt8], qa, kh[g][s8], kh[g][s8 + 2]);
            }
        }

#pragma unroll
        for (int h2 = 0; h2 < 2; h2++) {
            int rl = rloc0 + h2 * 8;
            float fv = h2 ? f1 : f0;
            float vmax = -1e30f;
#pragma unroll
            for (int nt = 0; nt < 8; nt++)
#pragma unroll
                for (int q = 0; q < 2; q++) {
                    int c = nt * 8 + cbase + q;
                    float sv = acc_s[nt][h2*2 + q] * 0.125f + fv * Ws[c - rl + 127];
                    acc_s[nt][h2*2 + q] = sv;
                    vmax = fmaxf(vmax, sv);
                }
            vmax = fmaxf(vmax, __shfl_xor_sync(0xffffffff, vmax, 1));
            vmax = fmaxf(vmax, __shfl_xor_sync(0xffffffff, vmax, 2));
            float mn = fmaxf(m_run[h2], vmax);
            float alpha = __expf(m_run[h2] - mn);
            m_run[h2] = mn;
            float rs = 0.f;
#pragma unroll
            for (int nt = 0; nt < 8; nt++)
#pragma unroll
                for (int q = 0; q < 2; q++) {
                    float p = __expf(acc_s[nt][h2*2 + q] - mn);
                    acc_s[nt][h2*2 + q] = p;
                    rs += p;
                }
            rs += __shfl_xor_sync(0xffffffff, rs, 1);
            rs += __shfl_xor_sync(0xffffffff, rs, 2);
            l_run[h2] = l_run[h2] * alpha + rs;
#pragma unroll
            for (int nt8 = 0; nt8 < 8; nt8++) {
                acc_o[nt8][h2*2 + 0] *= alpha;
                acc_o[nt8][h2*2 + 1] *= alpha;
            }
        }

#pragma unroll
        for (int kg = 0; kg < 4; kg++) {
            uint32_t ph[4], pl[4];
#pragma unroll
            for (int part = 0; part < 4; part++) {
                int tile = 2 * kg + (part >> 1);
                int o0 = (part & 1) * 2;
                float v0 = acc_s[tile][o0], v1 = acc_s[tile][o0 + 1];
                bf16 b0 = __float2bfloat16(v0), b1 = __float2bfloat16(v1);
                ph[part] = packbf(v0, v1);
                pl[part] = packbf(v0 - __bfloat162float(b0), v1 - __bfloat162float(b1));
            }
            int chunk = kg * 2 + (lane >> 4);
            uint32_t vh[4][4], vl[4][4];
#pragma unroll
            for (int ndt = 0; ndt < 4; ndt++) {
                int vr = ndt * 16 + (lane & 15);
                ldsm4(vh[ndt][0], vh[ndt][1], vh[ndt][2], vh[ndt][3], sb + AVTH + SWZ128(vr, chunk));
                ldsm4(vl[ndt][0], vl[ndt][1], vl[ndt][2], vl[ndt][3], sb + AVTL + SWZ128(vr, chunk));
            }
#pragma unroll
            for (int nd8 = 0; nd8 < 8; nd8++) {
                int g = nd8 >> 1, s8 = nd8 & 1;
                mma16816(acc_o[nd8], ph, vh[g][s8], vh[g][s8 + 2]);
                mma16816(acc_o[nd8], ph, vl[g][s8], vl[g][s8 + 2]);
                mma16816(acc_o[nd8], pl, vh[g][s8], vh[g][s8 + 2]);
            }
        }
    }

#pragma unroll
    for (int h2 = 0; h2 < 2; h2++) {
        float inv = 1.f / l_run[h2];
        int rg = t0 + rloc0 + h2 * 8;
#pragma unroll
        for (int nt8 = 0; nt8 < 8; nt8++) {
            int c = nt8 * 8 + cbase;
            float v0 = acc_o[nt8][h2*2 + 0] * inv;
            float v1 = acc_o[nt8][h2*2 + 1] * inv;
            size_t off = ((size_t)(b*T_ + rg))*DIM_ + h*64 + c;
            bf16_split2(v0, v1, Ohi, Olo, off);
        }
    }
}

// ---------------- GroupNorm finalize + apply ------------------------------------
__global__ void gn_finalize(int n) {
    int b = blockIdx.x;
    __shared__ double s1[128], s2[128];
    if (threadIdx.x < n) {
        s1[threadIdx.x] = g_PART[(b*128 + threadIdx.x)*2 + 0];
        s2[threadIdx.x] = g_PART[(b*128 + threadIdx.x)*2 + 1];
    }
    __syncthreads();
    if (threadIdx.x == 0) {
        double su = 0.0, sq = 0.0;
        for (int i = 0; i < n; i++) { su += s1[i]; sq += s2[i]; }
        double mean = su / (double)(T_*DIM_);
        double var = sq / (double)(T_*DIM_) - mean*mean;
        float inv = (float)(1.0 / sqrt(var + 1e-5));
        g_STATS[b] = make_float2((float)mean, inv);
    }
}
template<bool SILU>
__global__ void gn_apply(const float* __restrict__ x, const float* __restrict__ g,
                         const float* __restrict__ bt,
                         bf16* __restrict__ ohi, bf16* __restrict__ olo) {
    int idx = (blockIdx.x * 256 + threadIdx.x) * 2;
    int b = idx >> 19;
    int d = idx & (DIM_-1);
    float2 st = g_STATS[b];
    float2 xv = *(const float2*)(x + idx);
    float v0 = (xv.x - st.x) * st.y * g[d]     + bt[d];
    float v1 = (xv.y - st.x) * st.y * g[d + 1] + bt[d + 1];
    if (SILU) {
        v0 = v0 / (1.f + expf(-v0));
        v1 = v1 / (1.f + expf(-v1));
    }
    bf16_split2(v0, v1, ohi, olo, idx);
}

// ---------------- fused GLU + depthwise conv (+ GN partials) --------------------
__global__ void __launch_bounds__(256) glu_dwconv(
    const float* __restrict__ T1, const float* __restrict__ w,
    const float* __restrict__ wb, float* __restrict__ out)
{
    __shared__ float smv[94][64];
    __shared__ float smw[64][33];
    __shared__ double rsum[256], rsq[256];
    int b = blockIdx.z, t0 = blockIdx.x * 64, d0 = blockIdx.y * 64;
    int tid = threadIdx.x;
    for (int i = tid; i < 64 * KW; i += 256) {
        int dd = i / KW, j = i - dd * KW;
        smw[dd][j] = w[(size_t)(d0 + dd) * KW + j];
    }
    for (int i = tid; i < 94 * 64; i += 256) {
        int r = i >> 6, d = i & 63;
        int tt = t0 - 15 + r;
        float v = 0.f;
        if (tt >= 0 && tt < T_) {
            const float* base = T1 + ((size_t)(b*T_ + tt))*1024 + d0 + d;
            float a = base[0], gg = base[512];
            v = a / (1.f + expf(-gg));
        }
        smv[r][d] = v;
    }
    __syncthreads();
    int d = tid & 63, tr = tid >> 6;
    float wr[KW];
#pragma unroll
    for (int j = 0; j < KW; j++) wr[j] = smw[d][j];
    float bias = wb[d0 + d];
    double su = 0.0, sq = 0.0;
#pragma unroll 4
    for (int i = 0; i < 16; i++) {
        int t = tr * 16 + i;
        float acc = bias;
#pragma unroll
        for (int j = 0; j < KW; j++) acc += wr[j] * smv[t + j][d];
        out[((size_t)(b*T_ + t0 + t))*DIM_ + d0 + d] = acc;
        su += acc; sq += (double)acc * acc;
    }
    rsum[tid] = su; rsq[tid] = sq;
    __syncthreads();
    for (int st = 128; st > 0; st >>= 1) {
        if (tid < st) { rsum[tid] += rsum[tid + st]; rsq[tid] += rsq[tid + st]; }
        __syncthreads();
    }
    if (tid == 0) {
        int tidx = blockIdx.x * 8 + blockIdx.y;   // 0..127
        g_PART[(b*128 + tidx)*2 + 0] = rsum[0];
        g_PART[(b*128 + tidx)*2 + 1] = rsq[0];
    }
}

// ---------------- host ----------------------------------------------------------
static float* sym_f(const void* s) { void* p = nullptr; cudaGetSymbolAddress(&p, s); return (float*)p; }
static bf16* sym_b(const void* s) { void* p = nullptr; cudaGetSymbolAddress(&p, s); return (bf16*)p; }

#define SMEM_128 (512 + 3*(2*128*64 + 2*8192))
#define SMEM_64  (512 + 3*(2*64*64  + 2*8192))

extern "C" void kernel_launch(void* const* d_in, const int* in_sizes, int n_in,
                              void* d_out, int out_size) {
    const float* x      = (const float*)d_in[0];
    const float* ff1_w1 = (const float*)d_in[1];
    const float* ff1_b1 = (const float*)d_in[2];
    const float* ff1_w2 = (const float*)d_in[3];
    const float* ff1_b2 = (const float*)d_in[4];
    const float* qkv_w  = (const float*)d_in[5];
    const float* qkv_b  = (const float*)d_in[6];
    const float* out_w  = (const float*)d_in[7];
    const float* out_b  = (const float*)d_in[8];
    const float* gn1_g  = (const float*)d_in[9];
    const float* gn1_b  = (const float*)d_in[10];
    const float* pw1_w  = (const float*)d_in[11];
    const float* pw1_b  = (const float*)d_in[12];
    const float* dw_w   = (const float*)d_in[13];
    const float* dw_b   = (const float*)d_in[14];
    const float* gn2_g  = (const float*)d_in[15];
    const float* gn2_b  = (const float*)d_in[16];
    const float* pw2_w  = (const float*)d_in[17];
    const float* pw2_b  = (const float*)d_in[18];
    const float* ff2_w1 = (const float*)d_in[19];
    const float* ff2_b1 = (const float*)d_in[20];
    const float* ff2_w2 = (const float*)d_in[21];
    const float* ff2_b2 = (const float*)d_in[22];
    const float* rel_embed = (const float*)d_in[23];
    const float* gate_u = (const float*)d_in[24];
    const float* gate_w = (const float*)d_in[25];
    const float* scale_h = (const float*)d_in[26];

    float* S   = sym_f(g_S);
    float* T1  = sym_f(g_T1);
    float* QKV = sym_f(g_QKV);
    float* C1  = sym_f(g_C1);
    float* F   = sym_f(g_F);
    float* TAB = sym_f(g_TAB);
    bf16 *Shi = sym_b(g_Shi),  *Slo = sym_b(g_Slo);
    bf16 *Thi = sym_b(g_T1hi), *Tlo = sym_b(g_T1lo);
    bf16 *Ohi = sym_b(g_Ohi),  *Olo = sym_b(g_Olo);
    bf16 *Nhi = sym_b(g_N1hi), *Nlo = sym_b(g_N1lo);
    bf16 *Wf1a_hi = sym_b(g_Wf1a_hi), *Wf1a_lo = sym_b(g_Wf1a_lo);
    bf16 *Wf1b_hi = sym_b(g_Wf1b_hi), *Wf1b_lo = sym_b(g_Wf1b_lo);
    bf16 *Wqkv_hi = sym_b(g_Wqkv_hi), *Wqkv_lo = sym_b(g_Wqkv_lo);
    bf16 *Wout_hi = sym_b(g_Wout_hi), *Wout_lo = sym_b(g_Wout_lo);
    bf16 *Wpw1_hi = sym_b(g_Wpw1_hi), *Wpw1_lo = sym_b(g_Wpw1_lo);
    bf16 *Wpw2_hi = sym_b(g_Wpw2_hi), *Wpw2_lo = sym_b(g_Wpw2_lo);
    bf16 *Wf2a_hi = sym_b(g_Wf2a_hi), *Wf2a_lo = sym_b(g_Wf2a_lo);
    bf16 *Wf2b_hi = sym_b(g_Wf2b_hi), *Wf2b_lo = sym_b(g_Wf2b_lo);

    const int M = B_*T_;
    dim3 tb(32, 8);

    cudaFuncSetAttribute(gemm_mma<128,false,false>, cudaFuncAttributeMaxDynamicSharedMemorySize, SMEM_128);
    cudaFuncSetAttribute(gemm_mma<128,true,false>,  cudaFuncAttributeMaxDynamicSharedMemorySize, SMEM_128);
    cudaFuncSetAttribute(gemm_mma<64,false,false>,  cudaFuncAttributeMaxDynamicSharedMemorySize, SMEM_64);
    cudaFuncSetAttribute(gemm_mma<64,false,true>,   cudaFuncAttributeMaxDynamicSharedMemorySize, SMEM_64);
    cudaFuncSetAttribute(attn_mma, cudaFuncAttributeMaxDynamicSharedMemorySize, ATTN_SMEM);

    wsplit_all<<<5888, 256>>>(ff1_w1, ff1_w2, qkv_w, out_w, pw1_w, pw2_w, ff2_w1, ff2_w2);
    transpose_bdt_to_btd<<<dim3(T_/32, DIM_/32, B_), tb>>>(x, S, Shi, Slo);

    gemm_mma<128,true,false><<<dim3(FF_/128, M/128), 256, SMEM_128>>>(Shi, Slo, Wf1a_hi, Wf1a_lo, ff1_b1, nullptr, nullptr, Thi, Tlo, M, FF_, DIM_, 1.0f);
    gemm_mma<64,false,false><<<dim3(DIM_/128, M/64), 256, SMEM_64>>>(Thi, Tlo, Wf1b_hi, Wf1b_lo, ff1_b2, S, S, Shi, Slo, M, DIM_, FF_, 0.5f);
    gemm_mma<128,false,false><<<dim3(1536/128, M/128), 256, SMEM_128>>>(Shi, Slo, Wqkv_hi, Wqkv_lo, qkv_b, nullptr, QKV, nullptr, nullptr, M, 1536, DIM_, 1.0f);

    rel_table_kernel<<<(2047*H_ + 255)/256, 256>>>(rel_embed, TAB);
    gates_kernel<<<(B_*H_*T_)/8, 256>>>(QKV, gate_u, gate_w, scale_h, F);
    attn_mma<<<dim3(T_/128, H_, B_), 256, ATTN_SMEM>>>(QKV, F, TAB, Ohi, Olo);

    // out proj + residual; fused GN1 partials (grid (4,64): 64 tiles per batch)
    gemm_mma<64,false,true><<<dim3(DIM_/128, M/64), 256, SMEM_64>>>(Ohi, Olo, Wout_hi, Wout_lo, out_b, S, S, nullptr, nullptr, M, DIM_, DIM_, 1.0f);

    gn_finalize<<<B_, 64>>>(64);
    gn_apply<false><<<(B_*T_*DIM_)/512, 256>>>(S, gn1_g, gn1_b, Nhi, Nlo);

    gemm_mma<128,false,false><<<dim3(1024/128, M/128), 256, SMEM_128>>>(Nhi, Nlo, Wpw1_hi, Wpw1_lo, pw1_b, nullptr, T1, nullptr, nullptr, M, 1024, DIM_, 1.0f);

    glu_dwconv<<<dim3(T_/64, DIM_/64, B_), 256>>>(T1, dw_w, dw_b, C1);

    gn_finalize<<<B_, 128>>>(128);
    gn_apply<true><<<(B_*T_*DIM_)/512, 256>>>(C1, gn2_g, gn2_b, Nhi, Nlo);

    gemm_mma<64,false,false><<<dim3(DIM_/128, M/64), 256, SMEM_64>>>(Nhi, Nlo, Wpw2_hi, Wpw2_lo, pw2_b, S, S, Shi, Slo, M, DIM_, DIM_, 1.0f);

    gemm_mma<128,true,false><<<dim3(FF_/128, M/128), 256, SMEM_128>>>(Shi, Slo, Wf2a_hi, Wf2a_lo, ff2_b1, nullptr, nullptr, Thi, Tlo, M, FF_, DIM_, 1.0f);
    gemm_mma<64,false,false><<<dim3(DIM_/128, M/64), 256, SMEM_64>>>(Thi, Tlo, Wf2b_hi, Wf2b_lo, ff2_b2, S, S, nullptr, nullptr, M, DIM_, FF_, 0.5f);

    transpose_btd_to_bdt<<<dim3(DIM_/32, T_/32, B_), tb>>>(S, (float*)d_out);
}

// round 14
// speedup vs baseline: 1.0114x; 1.0114x over previous
#include <cuda_runtime.h>
#include <cuda_bf16.h>
#include <math.h>
#include <stdint.h>

#define B_ 4
#define T_ 1024
#define DIM_ 512
#define H_ 8
#define DH_ 64
#define FF_ 2048
#define KW 31

typedef __nv_bfloat16 bf16;

// ---------------- scratch (device globals) ------------------------------------
__device__ float g_S  [B_*T_*DIM_];
__device__ float g_T1 [B_*T_*FF_];
__device__ float g_QKV[B_*T_*3*DIM_];
__device__ float g_C1 [B_*T_*DIM_];
__device__ float g_F  [B_*H_*T_];
__device__ float g_TAB[H_*2048];
__device__ double g_PART[B_*128*2];
__device__ float2 g_STATS[B_];
__device__ bf16 g_Shi[B_*T_*DIM_],  g_Slo[B_*T_*DIM_];
__device__ bf16 g_T1hi[B_*T_*FF_],  g_T1lo[B_*T_*FF_];
__device__ bf16 g_Ohi[B_*T_*DIM_],  g_Olo[B_*T_*DIM_];
__device__ bf16 g_N1hi[B_*T_*DIM_], g_N1lo[B_*T_*DIM_];
__device__ bf16 g_Wf1a_hi[FF_*DIM_],  g_Wf1a_lo[FF_*DIM_];
__device__ bf16 g_Wf1b_hi[DIM_*FF_],  g_Wf1b_lo[DIM_*FF_];
__device__ bf16 g_Wqkv_hi[1536*DIM_], g_Wqkv_lo[1536*DIM_];
__device__ bf16 g_Wout_hi[DIM_*DIM_], g_Wout_lo[DIM_*DIM_];
__device__ bf16 g_Wpw1_hi[1024*DIM_], g_Wpw1_lo[1024*DIM_];
__device__ bf16 g_Wpw2_hi[DIM_*DIM_], g_Wpw2_lo[DIM_*DIM_];
__device__ bf16 g_Wf2a_hi[FF_*DIM_],  g_Wf2a_lo[FF_*DIM_];
__device__ bf16 g_Wf2b_hi[DIM_*FF_],  g_Wf2b_lo[DIM_*FF_];

// ---------------- helpers ------------------------------------------------------
__device__ __forceinline__ uint32_t smem_to_u32(const void* p) {
    uint32_t a;
    asm("{ .reg .u64 t; cvta.to.shared.u64 t, %1; cvt.u32.u64 %0, t; }" : "=r"(a) : "l"(p));
    return a;
}
__device__ __forceinline__ void cp16(uint32_t dst, const void* src) {
    asm volatile("cp.async.cg.shared.global [%0], [%1], 16;" :: "r"(dst), "l"(src));
}
#define CP_COMMIT() asm volatile("cp.async.commit_group;" ::: "memory")
#define CP_WAIT1()  asm volatile("cp.async.wait_group 1;" ::: "memory")

__device__ __forceinline__ void ldsm4(uint32_t& r0, uint32_t& r1, uint32_t& r2, uint32_t& r3, uint32_t addr) {
    asm volatile("ldmatrix.sync.aligned.m8n8.x4.shared.b16 {%0,%1,%2,%3}, [%4];"
                 : "=r"(r0), "=r"(r1), "=r"(r2), "=r"(r3) : "r"(addr));
}
__device__ __forceinline__ void mma16816(float* d, const uint32_t* a, uint32_t b0, uint32_t b1) {
    asm volatile("mma.sync.aligned.m16n8k16.row.col.f32.bf16.bf16.f32 "
                 "{%0,%1,%2,%3}, {%4,%5,%6,%7}, {%8,%9}, {%0,%1,%2,%3};"
                 : "+f"(d[0]), "+f"(d[1]), "+f"(d[2]), "+f"(d[3])
                 : "r"(a[0]), "r"(a[1]), "r"(a[2]), "r"(a[3]), "r"(b0), "r"(b1));
}
__device__ __forceinline__ void bf16_split(float v, bf16* hi, bf16* lo, size_t idx) {
    bf16 h = __float2bfloat16(v);
    hi[idx] = h;
    lo[idx] = __float2bfloat16(v - __bfloat162float(h));
}
__device__ __forceinline__ uint32_t packbf(float a, float b) {
    __nv_bfloat162 t = __floats2bfloat162_rn(a, b);
    return *(uint32_t*)&t;
}
__device__ __forceinline__ void bf16_split2(float v0, float v1, bf16* hi, bf16* lo, size_t off) {
    bf16 h0 = __float2bfloat16(v0), h1 = __float2bfloat16(v1);
    *(uint32_t*)(hi + off) = packbf(v0, v1);
    *(uint32_t*)(lo + off) = packbf(v0 - __bfloat162float(h0), v1 - __bfloat162float(h1));
}
__device__ __forceinline__ uint32_t swz(int r, int c) {
    return (uint32_t)(r * 64 + ((c ^ ((r >> 1) & 3)) << 4));
}
#define SWZ128(r, c8) ((uint32_t)((r)*128 + (((c8) ^ ((r)&7)) << 4)))

// ---------------- mma.sync GEMM ------------------------------------------------
// BM in {128,64}, BN=128. RED: emit GN partials. TOUT: write C transposed
// ((B,DIM,T) layout) via dead smem tiles instead of row-major C.
template<int BM>
__device__ __forceinline__ void stage_load2(
    uint32_t stg,
    const bf16* __restrict__ Ahi, const bf16* __restrict__ Alo,
    const bf16* __restrict__ Bhi, const bf16* __restrict__ Blo,
    int m0, int n0, int K, int kc, int tid)
{
    constexpr int ACH = BM * 4;
    constexpr int TC = 2 * ACH + 2 * 512;
    constexpr int ITER = TC / 256;
#pragma unroll
    for (int it = 0; it < ITER; it++) {
        int idx = it * 256 + tid;
        const bf16* base; int r, c; uint32_t moff; int grow;
        if (idx < 2 * ACH) {
            int mat = idx / ACH;
            int e = idx - mat * ACH;
            r = e >> 2; c = e & 3;
            base = mat ? Alo : Ahi;
            grow = m0 + r;
            moff = (uint32_t)mat * (BM * 64);
        } else {
            int e2 = idx - 2 * ACH;
            int mat = e2 >> 9;
            int e = e2 & 511;
            r = e >> 2; c = e & 3;
            base = mat ? Blo : Bhi;
            grow = n0 + r;
            moff = 2 * (BM * 64) + (uint32_t)mat * 8192;
        }
        cp16(stg + moff + swz(r, c), base + (size_t)grow * K + kc * 32 + c * 8);
    }
}

template<int BM, bool GELU, bool RED, bool TOUT>
__global__ void __launch_bounds__(256, 2) gemm_mma(
    const bf16* __restrict__ Ahi, const bf16* __restrict__ Alo,
    const bf16* __restrict__ Bhi, const bf16* __restrict__ Blo,
    const float* __restrict__ bias, const float* __restrict__ resid,
    float* __restrict__ C, bf16* __restrict__ Chi, bf16* __restrict__ Clo,
    int M, int N, int K, float alpha)
{
    constexpr int NW_N = (BM == 128) ? 2 : 4;
    constexpr int NT8  = (BM == 128) ? 8 : 4;
    constexpr int NBF  = NT8 / 2;
    constexpr int A_BYTES = BM * 64;
    constexpr int STG = 2 * A_BYTES + 2 * 8192;

    extern __shared__ char sm[];
    float* bias_s = (float*)sm;
    uint32_t tiles = smem_to_u32(sm) + 512;
    int tid = threadIdx.x, wid = tid >> 5, lane = tid & 31;
    int n0 = blockIdx.x * 128, m0 = blockIdx.y * BM;
    int wm = wid / NW_N, wn = wid % NW_N;

    if (tid < 128) bias_s[tid] = bias[n0 + tid];

    float acc[2][NT8][4];
#pragma unroll
    for (int i = 0; i < 2; i++)
#pragma unroll
        for (int j = 0; j < NT8; j++)
#pragma unroll
            for (int q = 0; q < 4; q++) acc[i][j][q] = 0.f;

    const int nk = K >> 5;
    stage_load2<BM>(tiles + 0 * STG, Ahi, Alo, Bhi, Blo, m0, n0, K, 0, tid);
    CP_COMMIT();
    stage_load2<BM>(tiles + 1 * STG, Ahi, Alo, Bhi, Blo, m0, n0, K, 1, tid);
    CP_COMMIT();

    int rowA = wm * 32 + (lane & 15);
    int rowB = wn * (NBF * 16) + (lane & 15);
    int csel = lane >> 4;

    int slot = 0;
    for (int kc = 0; kc < nk; kc++) {
        CP_WAIT1();
        __syncthreads();
        if (kc + 2 < nk) {
            int ns = slot + 2; if (ns >= 3) ns -= 3;
            stage_load2<BM>(tiles + ns * STG, Ahi, Alo, Bhi, Blo, m0, n0, K, kc + 2, tid);
            CP_COMMIT();
        }
        uint32_t stg = tiles + slot * STG;
#pragma unroll
        for (int kk = 0; kk < 2; kk++) {
            int chunk = kk * 2 + csel;
            uint32_t af[2][4], bh[NBF][4], bl[NBF][4];
#pragma unroll
            for (int mt = 0; mt < 2; mt++) {
                int r = rowA + mt * 16;
                ldsm4(af[mt][0], af[mt][1], af[mt][2], af[mt][3], stg + swz(r, chunk));
            }
#pragma unroll
            for (int nt = 0; nt < NBF; nt++) {
                int r = rowB + nt * 16;
                ldsm4(bh[nt][0], bh[nt][1], bh[nt][2], bh[nt][3], stg + 2 * A_BYTES + swz(r, chunk));
                ldsm4(bl[nt][0], bl[nt][1], bl[nt][2], bl[nt][3], stg + 2 * A_BYTES + 8192 + swz(r, chunk));
            }
#pragma unroll
            for (int mt = 0; mt < 2; mt++)
#pragma unroll
                for (int nt8 = 0; nt8 < NT8; nt8++) {
                    int g = nt8 >> 1, s = nt8 & 1;
                    mma16816(acc[mt][nt8], af[mt], bh[g][s], bh[g][s + 2]);
                    mma16816(acc[mt][nt8], af[mt], bl[g][s], bl[g][s + 2]);
                }
#pragma unroll
            for (int mt = 0; mt < 2; mt++) {
                int r = rowA + mt * 16;
                ldsm4(af[mt][0], af[mt][1], af[mt][2], af[mt][3], stg + A_BYTES + swz(r, chunk));
            }
#pragma unroll
            for (int mt = 0; mt < 2; mt++)
#pragma unroll
                for (int nt8 = 0; nt8 < NT8; nt8++) {
                    int g = nt8 >> 1, s = nt8 & 1;
                    mma16816(acc[mt][nt8], af[mt], bh[g][s], bh[g][s + 2]);
                }
        }
        slot++; if (slot >= 3) slot = 0;
    }

    float* ot = (float*)(sm + 512);   // TOUT staging (dead tiles region)
    if (TOUT) __syncthreads();        // ensure mainloop smem reads done before overwrite

    double su = 0.0, sq = 0.0;
    int rm = lane >> 2, cp = (lane & 3) * 2;
#pragma unroll
    for (int mt = 0; mt < 2; mt++) {
#pragma unroll
        for (int half = 0; half < 2; half++) {
            int mloc = wm * 32 + mt * 16 + half * 8 + rm;
            int m = m0 + mloc;
#pragma unroll
            for (int nt8 = 0; nt8 < NT8; nt8++) {
                int nl = wn * (NT8 * 8) + nt8 * 8 + cp;
                size_t off = (size_t)m * N + n0 + nl;
                float v0 = acc[mt][nt8][half * 2 + 0] + bias_s[nl];
                float v1 = acc[mt][nt8][half * 2 + 1] + bias_s[nl + 1];
                if (GELU) {
                    v0 = 0.5f * v0 * (1.0f + erff(v0 * 0.70710678f));
                    v1 = 0.5f * v1 * (1.0f + erff(v1 * 0.70710678f));
                }
                v0 *= alpha; v1 *= alpha;
                if (resid) {
                    float2 r = *(const float2*)(resid + off);
                    v0 += r.x; v1 += r.y;
                }
                if (TOUT) {
                    ot[mloc * 129 + nl] = v0;
                    ot[mloc * 129 + nl + 1] = v1;
                } else {
                    if (C) *(float2*)(C + off) = make_float2(v0, v1);
                    if (Chi) bf16_split2(v0, v1, Chi, Clo, off);
                }
                if (RED) {
                    su += (double)v0 + (double)v1;
                    sq += (double)v0 * v0 + (double)v1 * v1;
                }
            }
        }
    }
    if (TOUT) {
        // coalesced transposed write: C is (B, DIM, T)
        __syncthreads();
        int bb = m0 >> 10, tt0 = m0 & 1023;
#pragma unroll
        for (int i = 0; i < 32; i++) {
            int idx = i * 256 + tid;          // 8192 = 128 n x 64 t
            int nl = idx >> 6, tl = idx & 63;
            C[((size_t)(bb * DIM_ + n0 + nl)) * T_ + tt0 + tl] = ot[tl * 129 + nl];
        }
    }
    if (RED) {
        __syncthreads();
        double* rs = (double*)(sm + 512);
        rs[tid] = su; rs[256 + tid] = sq;
        __syncthreads();
        for (int st = 128; st > 0; st >>= 1) {
            if (tid < st) {
                rs[tid] += rs[tid + st];
                rs[256 + tid] += rs[256 + tid + st];
            }
            __syncthreads();
        }
        if (tid == 0) {
            int bb = m0 >> 10;
            int tidx = ((blockIdx.y & 15)) * gridDim.x + blockIdx.x;
            g_PART[(bb * 128 + tidx) * 2 + 0] = rs[0];
            g_PART[(bb * 128 + tidx) * 2 + 1] = rs[256];
        }
    }
}

// ---------------- fused weight split (packed stores) ----------------------------
__device__ void do_split_t(float (*t)[33], const float* __restrict__ W, bf16* hi, bf16* lo,
                           int K, int N, int tile) {
    int kt = K / 32;
    int k0 = (tile % kt) * 32, n0 = (tile / kt) * 32;
    int tx = threadIdx.x & 31, ty = threadIdx.x >> 5;
    for (int r = ty; r < 32; r += 8)
        t[r][tx] = W[(size_t)(k0 + r) * N + n0 + tx];
    __syncthreads();
    int tx2 = threadIdx.x & 15, ty2 = threadIdx.x >> 4;
    for (int rr = ty2; rr < 32; rr += 16)
        bf16_split2(t[2*tx2][rr], t[2*tx2+1][rr], hi, lo, (size_t)(n0 + rr) * K + k0 + 2*tx2);
}
__device__ void do_split_d(const float* __restrict__ W, bf16* hi, bf16* lo, int tile) {
    int i = tile * 1024 + threadIdx.x * 4;
    float4 v = *(const float4*)(W + i);
    bf16_split2(v.x, v.y, hi, lo, i);
    bf16_split2(v.z, v.w, hi, lo, i + 2);
}
__global__ void wsplit_all(const float* ff1_w1, const float* ff1_w2, const float* qkv_w,
                           const float* out_w, const float* pw1_w, const float* pw2_w,
                           const float* ff2_w1, const float* ff2_w2) {
    __shared__ float t[32][33];
    int b = blockIdx.x;
    if      (b < 1024) do_split_t(t, ff1_w1, g_Wf1a_hi, g_Wf1a_lo, DIM_, FF_, b);
    else if (b < 2048) do_split_t(t, ff1_w2, g_Wf1b_hi, g_Wf1b_lo, FF_, DIM_, b - 1024);
    else if (b < 2816) do_split_t(t, qkv_w,  g_Wqkv_hi, g_Wqkv_lo, DIM_, 1536, b - 2048);
    else if (b < 3072) do_split_t(t, out_w,  g_Wout_hi, g_Wout_lo, DIM_, DIM_, b - 2816);
    else if (b < 3584) do_split_d(pw1_w, g_Wpw1_hi, g_Wpw1_lo, b - 3072);
    else if (b < 3840) do_split_d(pw2_w, g_Wpw2_hi, g_Wpw2_lo, b - 3584);
    else if (b < 4864) do_split_t(t, ff2_w1, g_Wf2a_hi, g_Wf2a_lo, DIM_, FF_, b - 3840);
    else               do_split_t(t, ff2_w2, g_Wf2b_hi, g_Wf2b_lo, FF_, DIM_, b - 4864);
}

// ---------------- input transpose -----------------------------------------------
__global__ void transpose_bdt_to_btd(const float* __restrict__ in, float* __restrict__ out,
                                     bf16* __restrict__ ohi, bf16* __restrict__ olo) {
    __shared__ float tile[32][33];
    int b = blockIdx.z;
    int t0 = blockIdx.x * 32, d0 = blockIdx.y * 32;
    for (int i = threadIdx.y; i < 32; i += 8)
        tile[i][threadIdx.x] = in[((size_t)b*DIM_ + d0 + i)*T_ + t0 + threadIdx.x];
    __syncthreads();
    int tid = threadIdx.y * 32 + threadIdx.x;
    int dx = (tid & 15) * 2;
    int r0 = tid >> 4;
#pragma unroll
    for (int rstep = 0; rstep < 2; rstep++) {
        int i = r0 + rstep * 16;
        float v0 = tile[dx][i], v1 = tile[dx + 1][i];
        size_t o = ((size_t)b*T_ + t0 + i)*DIM_ + d0 + dx;
        *(float2*)(out + o) = make_float2(v0, v1);
        bf16_split2(v0, v1, ohi, olo, o);
    }
}

// ---------------- rel-bias table + gates ----------------------------------------
__global__ void rel_table_kernel(const float* __restrict__ rel_embed, float* __restrict__ tab) {
    int idx = blockIdx.x * 256 + threadIdx.x;
    if (idx >= 2047 * H_) return;
    int rr = idx >> 3, h = idx & 7;
    int rel = rr - 1023;
    int sign = (rel >= 0) ? 1 : 0;
    int ap = rel >= 0 ? rel : -rel;
    int bidx;
    if (ap < 80) bidx = ap;
    else {
        float lr = logf((float)ap / 80.0f) / 2.3025851f;
        int lp = (int)(80.0f + lr * 80.0f);
        bidx = lp < 159 ? lp : 159;
    }
    int bucket = bidx + sign * 160;
    bucket = bucket < 0 ? 0 : (bucket > 319 ? 319 : bucket);
    tab[h * 2048 + rr] = rel_embed[bucket * H_ + h];
}
__global__ void gates_kernel(const float* __restrict__ QKV, const float* __restrict__ gu,
                             const float* __restrict__ gw, const float* __restrict__ sh,
                             float* __restrict__ F) {
    int row = blockIdx.x * 8 + (threadIdx.x >> 5);
    int lane = threadIdx.x & 31;
    int t = row & (T_-1);
    int bh = row >> 10;
    int h = bh & (H_-1), b = bh >> 3;
    const float* q = QKV + ((size_t)(b*T_ + t))*1536 + h*DH_;
    float su = 0.f, sw = 0.f;
    for (int d = lane; d < DH_; d += 32) {
        float qv = q[d];
        su += qv * gu[h*DH_ + d];
        sw += qv * gw[h*DH_ + d];
    }
#pragma unroll
    for (int m = 16; m; m >>= 1) {
        su += __shfl_xor_sync(0xffffffff, su, m);
        sw += __shfl_xor_sync(0xffffffff, sw, m);
    }
    if (lane == 0) {
        float g_u = 1.f / (1.f + expf(-su));
        float g_w = 1.f / (1.f + expf(-sw));
        F[row] = 1.f + g_u + (1.f - g_u) * sh[h] * g_w;
    }
}

// ---------------- flash attention on mma.sync -----------------------------------
#define AQHI 0
#define AQLO 16384
#define AKHI 32768
#define AKLO 40960
#define AVTH 49152
#define AVTL 57344
#define AWOF 65536
#define ATTN_SMEM (65536 + 768)

__global__ void __launch_bounds__(256, 2) attn_mma(
    const float* __restrict__ QKV, const float* __restrict__ F,
    const float* __restrict__ TAB, bf16* __restrict__ Ohi, bf16* __restrict__ Olo)
{
    extern __shared__ char sma[];
    uint32_t sb = smem_to_u32(sma);
    float* Ws = (float*)(sma + AWOF);

    int tid = threadIdx.x, wid = tid >> 5, lane = tid & 31;
    int t0 = blockIdx.x * 128, h = blockIdx.y, b = blockIdx.z;

#pragma unroll
    for (int i = 0; i < 4; i++) {
        int task = i * 256 + tid;
        int r = task >> 3, c8 = task & 7;
        const float* src = QKV + ((size_t)(b*T_ + t0 + r))*1536 + h*64 + c8*8;
        float4 v0 = *(const float4*)src, v1 = *(const float4*)(src + 4);
        float vv[8] = {v0.x, v0.y, v0.z, v0.w, v1.x, v1.y, v1.z, v1.w};
        bf16 h8[8], l8[8];
#pragma unroll
        for (int j = 0; j < 8; j++) {
            h8[j] = __float2bfloat16(vv[j]);
            l8[j] = __float2bfloat16(vv[j] - __bfloat162float(h8[j]));
        }
        uint32_t off = SWZ128(r, c8);
        *(uint4*)(sma + AQHI + off) = *(uint4*)h8;
        *(uint4*)(sma + AQLO + off) = *(uint4*)l8;
    }
    int rloc0 = wid * 16 + (lane >> 2);
    int cbase = (lane & 3) * 2;
    float f0 = F[((b*H_ + h) << 10) + t0 + rloc0];
    float f1 = F[((b*H_ + h) << 10) + t0 + rloc0 + 8];

    float m_run[2] = {-1e30f, -1e30f}, l_run[2] = {0.f, 0.f};
    float acc_o[8][4];
#pragma unroll
    for (int i = 0; i < 8; i++)
#pragma unroll
        for (int q = 0; q < 4; q++) acc_o[i][q] = 0.f;

    for (int st = 0; st < T_/64; st++) {
        int s0 = st * 64;
        __syncthreads();
#pragma unroll
        for (int i = 0; i < 2; i++) {
            int task = i * 256 + tid;
            int r = task >> 3, c8 = task & 7;
            const float* src = QKV + ((size_t)(b*T_ + s0 + r))*1536 + 512 + h*64 + c8*8;
            float4 v0 = *(const float4*)src, v1 = *(const float4*)(src + 4);
            float vv[8] = {v0.x, v0.y, v0.z, v0.w, v1.x, v1.y, v1.z, v1.w};
            bf16 h8[8], l8[8];
#pragma unroll
            for (int j = 0; j < 8; j++) {
                h8[j] = __float2bfloat16(vv[j]);
                l8[j] = __float2bfloat16(vv[j] - __bfloat162float(h8[j]));
            }
            uint32_t off = SWZ128(r, c8);
            *(uint4*)(sma + AKHI + off) = *(uint4*)h8;
            *(uint4*)(sma + AKLO + off) = *(uint4*)l8;
        }
        {
            int sp = (tid & 31) * 2;
            int dg = (tid >> 5) * 8;
            const float* src0 = QKV + ((size_t)(b*T_ + s0 + sp))*1536 + 1024 + h*64 + dg;
            const float* src1 = src0 + 1536;
            float4 a0 = *(const float4*)src0, a1 = *(const float4*)(src0 + 4);
            float4 b0 = *(const float4*)src1, b1 = *(const float4*)(src1 + 4);
            float r0v[8] = {a0.x, a0.y, a0.z, a0.w, a1.x, a1.y, a1.z, a1.w};
            float r1v[8] = {b0.x, b0.y, b0.z, b0.w, b1.x, b1.y, b1.z, b1.w};
#pragma unroll
            for (int j = 0; j < 8; j++) {
                int d = dg + j;
                uint32_t off = (uint32_t)(d*128 + ((((sp >> 3) ^ (d & 7))) << 4) + (sp & 7)*2);
                float v0 = r0v[j], v1 = r1v[j];
                bf16 h0 = __float2bfloat16(v0), h1 = __float2bfloat16(v1);
                *(uint32_t*)(sma + AVTH + off) = packbf(v0, v1);
                *(uint32_t*)(sma + AVTL + off) =
                    packbf(v0 - __bfloat162float(h0), v1 - __bfloat162float(h1));
            }
        }
        if (tid < 192) {
            int gidx = s0 - t0 + 896 + tid;
            gidx = gidx < 0 ? 0 : (gidx > 2046 ? 2046 : gidx);
            Ws[tid] = TAB[h*2048 + gidx];
        }
        __syncthreads();

        float acc_s[8][4];
#pragma unroll
        for (int i = 0; i < 8; i++)
#pragma unroll
            for (int q = 0; q < 4; q++) acc_s[i][q] = 0.f;
        int qr = wid * 16 + (lane & 15);
#pragma unroll
        for (int ks = 0; ks < 4; ks++) {
            int chunk = ks * 2 + (lane >> 4);
            uint32_t qa[4], kh[4][4], kl[4][4];
            ldsm4(qa[0], qa[1], qa[2], qa[3], sb + AQHI + SWZ128(qr, chunk));
#pragma unroll
            for (int nt = 0; nt < 4; nt++) {
                int kr = nt * 16 + (lane & 15);
                ldsm4(kh[nt][0], kh[nt][1], kh[nt][2], kh[nt][3], sb + AKHI + SWZ128(kr, chunk));
                ldsm4(kl[nt][0], kl[nt][1], kl[nt][2], kl[nt][3], sb + AKLO + SWZ128(kr, chunk));
            }
#pragma unroll
            for (int nt8 = 0; nt8 < 8; nt8++) {
                int g = nt8 >> 1, s8 = nt8 & 1;
                mma16816(acc_s[nt8], qa, kh[g][s8], kh[g][s8 + 2]);
                mma16816(acc_s[nt8], qa, kl[g][s8], kl[g][s8 + 2]);
            }
            ldsm4(qa[0], qa[1], qa[2], qa[3], sb + AQLO + SWZ128(qr, chunk));
#pragma unroll
            for (int nt8 = 0; nt8 < 8; nt8++) {
                int g = nt8 >> 1, s8 = nt8 & 1;
                mma16816(acc_s[nt8], qa, kh[g][s8], kh[g][s8 + 2]);
            }
        }

#pragma unroll
        for (int h2 = 0; h2 < 2; h2++) {
            int rl = rloc0 + h2 * 8;
            float fv = h2 ? f1 : f0;
            float vmax = -1e30f;
#pragma unroll
            for (int nt = 0; nt < 8; nt++)
#pragma unroll
                for (int q = 0; q < 2; q++) {
                    int c = nt * 8 + cbase + q;
                    float sv = acc_s[nt][h2*2 + q] * 0.125f + fv * Ws[c - rl + 127];
                    acc_s[nt][h2*2 + q] = sv;
                    vmax = fmaxf(vmax, sv);
                }
            vmax = fmaxf(vmax, __shfl_xor_sync(0xffffffff, vmax, 1));
            vmax = fmaxf(vmax, __shfl_xor_sync(0xffffffff, vmax, 2));
            float mn = fmaxf(m_run[h2], vmax);
            float alpha = __expf(m_run[h2] - mn);
            m_run[h2] = mn;
            float rs = 0.f;
#pragma unroll
            for (int nt = 0; nt < 8; nt++)
#pragma unroll
                for (int q = 0; q < 2; q++) {
                    float p = __expf(acc_s[nt][h2*2 + q] - mn);
                    acc_s[nt][h2*2 + q] = p;
                    rs += p;
                }
            rs += __shfl_xor_sync(0xffffffff, rs, 1);
            rs += __shfl_xor_sync(0xffffffff, rs, 2);
            l_run[h2] = l_run[h2] * alpha + rs;
#pragma unroll
            for (int nt8 = 0; nt8 < 8; nt8++) {
                acc_o[nt8][h2*2 + 0] *= alpha;
                acc_o[nt8][h2*2 + 1] *= alpha;
            }
        }

#pragma unroll
        for (int kg = 0; kg < 4; kg++) {
            uint32_t ph[4], pl[4];
#pragma unroll
            for (int part = 0; part < 4; part++) {
                int tile = 2 * kg + (part >> 1);
                int o0 = (part & 1) * 2;
                float v0 = acc_s[tile][o0], v1 = acc_s[tile][o0 + 1];
                bf16 b0 = __float2bfloat16(v0), b1 = __float2bfloat16(v1);
                ph[part] = packbf(v0, v1);
                pl[part] = packbf(v0 - __bfloat162float(b0), v1 - __bfloat162float(b1));
            }
            int chunk = kg * 2 + (lane >> 4);
            uint32_t vh[4][4], vl[4][4];
#pragma unroll
            for (int ndt = 0; ndt < 4; ndt++) {
                int vr = ndt * 16 + (lane & 15);
                ldsm4(vh[ndt][0], vh[ndt][1], vh[ndt][2], vh[ndt][3], sb + AVTH + SWZ128(vr, chunk));
                ldsm4(vl[ndt][0], vl[ndt][1], vl[ndt][2], vl[ndt][3], sb + AVTL + SWZ128(vr, chunk));
            }
#pragma unroll
            for (int nd8 = 0; nd8 < 8; nd8++) {
                int g = nd8 >> 1, s8 = nd8 & 1;
                mma16816(acc_o[nd8], ph, vh[g][s8], vh[g][s8 + 2]);
                mma16816(acc_o[nd8], ph, vl[g][s8], vl[g][s8 + 2]);
                mma16816(acc_o[nd8], pl, vh[g][s8], vh[g][s8 + 2]);
            }
        }
    }

#pragma unroll
    for (int h2 = 0; h2 < 2; h2++) {
        float inv = 1.f / l_run[h2];
        int rg = t0 + rloc0 + h2 * 8;
#pragma unroll
        for (int nt8 = 0; nt8 < 8; nt8++) {
            int c = nt8 * 8 + cbase;
            float v0 = acc_o[nt8][h2*2 + 0] * inv;
            float v1 = acc_o[nt8][h2*2 + 1] * inv;
            size_t off = ((size_t)(b*T_ + rg))*DIM_ + h*64 + c;
            bf16_split2(v0, v1, Ohi, Olo, off);
        }
    }
}

// ---------------- GroupNorm finalize + apply ------------------------------------
__global__ void gn_finalize(int n) {
    int b = blockIdx.x;
    __shared__ double s1[128], s2[128];
    if (threadIdx.x < n) {
        s1[threadIdx.x] = g_PART[(b*128 + threadIdx.x)*2 + 0];
        s2[threadIdx.x] = g_PART[(b*128 + threadIdx.x)*2 + 1];
    }
    __syncthreads();
    if (threadIdx.x == 0) {
        double su = 0.0, sq = 0.0;
        for (int i = 0; i < n; i++) { su += s1[i]; sq += s2[i]; }
        double mean = su / (double)(T_*DIM_);
        double var = sq / (double)(T_*DIM_) - mean*mean;
        float inv = (float)(1.0 / sqrt(var + 1e-5));
        g_STATS[b] = make_float2((float)mean, inv);
    }
}
template<bool SILU>
__global__ void gn_apply(const float* __restrict__ x, const float* __restrict__ g,
                         const float* __restrict__ bt,
                         bf16* __restrict__ ohi, bf16* __restrict__ olo) {
    int idx = (blockIdx.x * 256 + threadIdx.x) * 2;
    int b = idx >> 19;
    int d = idx & (DIM_-1);
    float2 st = g_STATS[b];
    float2 xv = *(const float2*)(x + idx);
    float v0 = (xv.x - st.x) * st.y * g[d]     + bt[d];
    float v1 = (xv.y - st.x) * st.y * g[d + 1] + bt[d + 1];
    if (SILU) {
        v0 = v0 / (1.f + expf(-v0));
        v1 = v1 / (1.f + expf(-v1));
    }
    bf16_split2(v0, v1, ohi, olo, idx);
}

// ---------------- fused GLU + depthwise conv (+ GN partials) --------------------
__global__ void __launch_bounds__(256) glu_dwconv(
    const float* __restrict__ T1, const float* __restrict__ w,
    const float* __restrict__ wb, float* __restrict__ out)
{
    __shared__ float smv[94][64];
    __shared__ float smw[64][33];
    __shared__ double rsum[256], rsq[256];
    int b = blockIdx.z, t0 = blockIdx.x * 64, d0 = blockIdx.y * 64;
    int tid = threadIdx.x;
    for (int i = tid; i < 64 * KW; i += 256) {
        int dd = i / KW, j = i - dd * KW;
        smw[dd][j] = w[(size_t)(d0 + dd) * KW + j];
    }
    for (int i = tid; i < 94 * 64; i += 256) {
        int r = i >> 6, d = i & 63;
        int tt = t0 - 15 + r;
        float v = 0.f;
        if (tt >= 0 && tt < T_) {
            const float* base = T1 + ((size_t)(b*T_ + tt))*1024 + d0 + d;
            float a = base[0], gg = base[512];
            v = a / (1.f + expf(-gg));
        }
        smv[r][d] = v;
    }
    __syncthreads();
    int d = tid & 63, tr = tid >> 6;
    float wr[KW];
#pragma unroll
    for (int j = 0; j < KW; j++) wr[j] = smw[d][j];
    float bias = wb[d0 + d];
    double su = 0.0, sq = 0.0;
#pragma unroll 4
    for (int i = 0; i < 16; i++) {
        int t = tr * 16 + i;
        float acc = bias;
#pragma unroll
        for (int j = 0; j < KW; j++) acc += wr[j] * smv[t + j][d];
        out[((size_t)(b*T_ + t0 + t))*DIM_ + d0 + d] = acc;
        su += acc; sq += (double)acc * acc;
    }
    rsum[tid] = su; rsq[tid] = sq;
    __syncthreads();
    for (int st = 128; st > 0; st >>= 1) {
        if (tid < st) { rsum[tid] += rsum[tid + st]; rsq[tid] += rsq[tid + st]; }
        __syncthreads();
    }
    if (tid == 0) {
        int tidx = blockIdx.x * 8 + blockIdx.y;
        g_PART[(b*128 + tidx)*2 + 0] = rsum[0];
        g_PART[(b*128 + tidx)*2 + 1] = rsq[0];
    }
}

// ---------------- host ----------------------------------------------------------
static float* sym_f(const void* s) { void* p = nullptr; cudaGetSymbolAddress(&p, s); return (float*)p; }
static bf16* sym_b(const void* s) { void* p = nullptr; cudaGetSymbolAddress(&p, s); return (bf16*)p; }

#define SMEM_128 (512 + 3*(2*128*64 + 2*8192))
#define SMEM_64  (512 + 3*(2*64*64  + 2*8192))

extern "C" void kernel_launch(void* const* d_in, const int* in_sizes, int n_in,
                              void* d_out, int out_size) {
    const float* x      = (const float*)d_in[0];
    const float* ff1_w1 = (const float*)d_in[1];
    const float* ff1_b1 = (const float*)d_in[2];
    const float* ff1_w2 = (const float*)d_in[3];
    const float* ff1_b2 = (const float*)d_in[4];
    const float* qkv_w  = (const float*)d_in[5];
    const float* qkv_b  = (const float*)d_in[6];
    const float* out_w  = (const float*)d_in[7];
    const float* out_b  = (const float*)d_in[8];
    const float* gn1_g  = (const float*)d_in[9];
    const float* gn1_b  = (const float*)d_in[10];
    const float* pw1_w  = (const float*)d_in[11];
    const float* pw1_b  = (const float*)d_in[12];
    const float* dw_w   = (const float*)d_in[13];
    const float* dw_b   = (const float*)d_in[14];
    const float* gn2_g  = (const float*)d_in[15];
    const float* gn2_b  = (const float*)d_in[16];
    const float* pw2_w  = (const float*)d_in[17];
    const float* pw2_b  = (const float*)d_in[18];
    const float* ff2_w1 = (const float*)d_in[19];
    const float* ff2_b1 = (const float*)d_in[20];
    const float* ff2_w2 = (const float*)d_in[21];
    const float* ff2_b2 = (const float*)d_in[22];
    const float* rel_embed = (const float*)d_in[23];
    const float* gate_u = (const float*)d_in[24];
    const float* gate_w = (const float*)d_in[25];
    const float* scale_h = (const float*)d_in[26];

    float* S   = sym_f(g_S);
    float* T1  = sym_f(g_T1);
    float* QKV = sym_f(g_QKV);
    float* C1  = sym_f(g_C1);
    float* F   = sym_f(g_F);
    float* TAB = sym_f(g_TAB);
    bf16 *Shi = sym_b(g_Shi),  *Slo = sym_b(g_Slo);
    bf16 *Thi = sym_b(g_T1hi), *Tlo = sym_b(g_T1lo);
    bf16 *Ohi = sym_b(g_Ohi),  *Olo = sym_b(g_Olo);
    bf16 *Nhi = sym_b(g_N1hi), *Nlo = sym_b(g_N1lo);
    bf16 *Wf1a_hi = sym_b(g_Wf1a_hi), *Wf1a_lo = sym_b(g_Wf1a_lo);
    bf16 *Wf1b_hi = sym_b(g_Wf1b_hi), *Wf1b_lo = sym_b(g_Wf1b_lo);
    bf16 *Wqkv_hi = sym_b(g_Wqkv_hi), *Wqkv_lo = sym_b(g_Wqkv_lo);
    bf16 *Wout_hi = sym_b(g_Wout_hi), *Wout_lo = sym_b(g_Wout_lo);
    bf16 *Wpw1_hi = sym_b(g_Wpw1_hi), *Wpw1_lo = sym_b(g_Wpw1_lo);
    bf16 *Wpw2_hi = sym_b(g_Wpw2_hi), *Wpw2_lo = sym_b(g_Wpw2_lo);
    bf16 *Wf2a_hi = sym_b(g_Wf2a_hi), *Wf2a_lo = sym_b(g_Wf2a_lo);
    bf16 *Wf2b_hi = sym_b(g_Wf2b_hi), *Wf2b_lo = sym_b(g_Wf2b_lo);

    const int M = B_*T_;
    dim3 tb(32, 8);

    cudaFuncSetAttribute(gemm_mma<128,false,false,false>, cudaFuncAttributeMaxDynamicSharedMemorySize, SMEM_128);
    cudaFuncSetAttribute(gemm_mma<128,true,false,false>,  cudaFuncAttributeMaxDynamicSharedMemorySize, SMEM_128);
    cudaFuncSetAttribute(gemm_mma<64,false,false,false>,  cudaFuncAttributeMaxDynamicSharedMemorySize, SMEM_64);
    cudaFuncSetAttribute(gemm_mma<64,false,true,false>,   cudaFuncAttributeMaxDynamicSharedMemorySize, SMEM_64);
    cudaFuncSetAttribute(gemm_mma<64,false,false,true>,   cudaFuncAttributeMaxDynamicSharedMemorySize, SMEM_64);
    cudaFuncSetAttribute(attn_mma, cudaFuncAttributeMaxDynamicSharedMemorySize, ATTN_SMEM);

    wsplit_all<<<5888, 256>>>(ff1_w1, ff1_w2, qkv_w, out_w, pw1_w, pw2_w, ff2_w1, ff2_w2);
    transpose_bdt_to_btd<<<dim3(T_/32, DIM_/32, B_), tb>>>(x, S, Shi, Slo);

    gemm_mma<128,true,false,false><<<dim3(FF_/128, M/128), 256, SMEM_128>>>(Shi, Slo, Wf1a_hi, Wf1a_lo, ff1_b1, nullptr, nullptr, Thi, Tlo, M, FF_, DIM_, 1.0f);
    gemm_mma<64,false,false,false><<<dim3(DIM_/128, M/64), 256, SMEM_64>>>(Thi, Tlo, Wf1b_hi, Wf1b_lo, ff1_b2, S, S, Shi, Slo, M, DIM_, FF_, 0.5f);
    gemm_mma<128,false,false,false><<<dim3(1536/128, M/128), 256, SMEM_128>>>(Shi, Slo, Wqkv_hi, Wqkv_lo, qkv_b, nullptr, QKV, nullptr, nullptr, M, 1536, DIM_, 1.0f);

    rel_table_kernel<<<(2047*H_ + 255)/256, 256>>>(rel_embed, TAB);
    gates_kernel<<<(B_*H_*T_)/8, 256>>>(QKV, gate_u, gate_w, scale_h, F);
    attn_mma<<<dim3(T_/128, H_, B_), 256, ATTN_SMEM>>>(QKV, F, TAB, Ohi, Olo);

    // out proj + residual; fused GN1 partials
    gemm_mma<64,false,true,false><<<dim3(DIM_/128, M/64), 256, SMEM_64>>>(Ohi, Olo, Wout_hi, Wout_lo, out_b, S, S, nullptr, nullptr, M, DIM_, DIM_, 1.0f);

    gn_finalize<<<B_, 64>>>(64);
    gn_apply<false><<<(B_*T_*DIM_)/512, 256>>>(S, gn1_g, gn1_b, Nhi, Nlo);

    gemm_mma<128,false,false,false><<<dim3(1024/128, M/128), 256, SMEM_128>>>(Nhi, Nlo, Wpw1_hi, Wpw1_lo, pw1_b, nullptr, T1, nullptr, nullptr, M, 1024, DIM_, 1.0f);

    glu_dwconv<<<dim3(T_/64, DIM_/64, B_), 256>>>(T1, dw_w, dw_b, C1);

    gn_finalize<<<B_, 128>>>(128);
    gn_apply<true><<<(B_*T_*DIM_)/512, 256>>>(C1, gn2_g, gn2_b, Nhi, Nlo);

    gemm_mma<64,false,false,false><<<dim3(DIM_/128, M/64), 256, SMEM_64>>>(Nhi, Nlo, Wpw2_hi, Wpw2_lo, pw2_b, S, S, Shi, Slo, M, DIM_, DIM_, 1.0f);

    gemm_mma<128,true,false,false><<<dim3(FF_/128, M/128), 256, SMEM_128>>>(Shi, Slo, Wf2a_hi, Wf2a_lo, ff2_b1, nullptr, nullptr, Thi, Tlo, M, FF_, DIM_, 1.0f);
    // FF2b: writes directly to d_out, transposed (B, DIM, T); no transpose kernel
    gemm_mma<64,false,false,true><<<dim3(DIM_/128, M/64), 256, SMEM_64>>>(Thi, Tlo, Wf2b_hi, Wf2b_lo, ff2_b2, S, (float*)d_out, nullptr, nullptr, M, DIM_, FF_, 0.5f);
}

// round 15
// speedup vs baseline: 1.0209x; 1.0095x over previous
#include <cuda_runtime.h>
#include <cuda_bf16.h>
#include <math.h>
#include <stdint.h>

#define B_ 4
#define T_ 1024
#define DIM_ 512
#define H_ 8
#define DH_ 64
#define FF_ 2048
#define KW 31

typedef __nv_bfloat16 bf16;

// ---------------- scratch (device globals) ------------------------------------
__device__ float g_S  [B_*T_*DIM_];
__device__ float g_T1 [B_*T_*FF_];
__device__ float g_QKV[B_*T_*3*DIM_];
__device__ float g_C1 [B_*T_*DIM_];
__device__ float g_F  [B_*H_*T_];
__device__ float g_TAB[H_*2048];
__device__ double g_PART[B_*128*2];
__device__ float2 g_STATS[B_];
__device__ bf16 g_Shi[B_*T_*DIM_],  g_Slo[B_*T_*DIM_];
__device__ bf16 g_T1hi[B_*T_*FF_],  g_T1lo[B_*T_*FF_];
__device__ bf16 g_Ohi[B_*T_*DIM_],  g_Olo[B_*T_*DIM_];
__device__ bf16 g_N1hi[B_*T_*DIM_], g_N1lo[B_*T_*DIM_];
__device__ bf16 g_Wf1a_hi[FF_*DIM_],  g_Wf1a_lo[FF_*DIM_];
__device__ bf16 g_Wf1b_hi[DIM_*FF_],  g_Wf1b_lo[DIM_*FF_];
__device__ bf16 g_Wqkv_hi[1536*DIM_], g_Wqkv_lo[1536*DIM_];
__device__ bf16 g_Wout_hi[DIM_*DIM_], g_Wout_lo[DIM_*DIM_];
__device__ bf16 g_Wpw1_hi[1024*DIM_], g_Wpw1_lo[1024*DIM_];
__device__ bf16 g_Wpw2_hi[DIM_*DIM_], g_Wpw2_lo[DIM_*DIM_];
__device__ bf16 g_Wf2a_hi[FF_*DIM_],  g_Wf2a_lo[FF_*DIM_];
__device__ bf16 g_Wf2b_hi[DIM_*FF_],  g_Wf2b_lo[DIM_*FF_];

// ---------------- helpers ------------------------------------------------------
__device__ __forceinline__ uint32_t smem_to_u32(const void* p) {
    uint32_t a;
    asm("{ .reg .u64 t; cvta.to.shared.u64 t, %1; cvt.u32.u64 %0, t; }" : "=r"(a) : "l"(p));
    return a;
}
__device__ __forceinline__ void cp16(uint32_t dst, const void* src) {
    asm volatile("cp.async.cg.shared.global [%0], [%1], 16;" :: "r"(dst), "l"(src));
}
#define CP_COMMIT() asm volatile("cp.async.commit_group;" ::: "memory")
#define CP_WAIT1()  asm volatile("cp.async.wait_group 1;" ::: "memory")

__device__ __forceinline__ void ldsm4(uint32_t& r0, uint32_t& r1, uint32_t& r2, uint32_t& r3, uint32_t addr) {
    asm volatile("ldmatrix.sync.aligned.m8n8.x4.shared.b16 {%0,%1,%2,%3}, [%4];"
                 : "=r"(r0), "=r"(r1), "=r"(r2), "=r"(r3) : "r"(addr));
}
__device__ __forceinline__ void mma16816(float* d, const uint32_t* a, uint32_t b0, uint32_t b1) {
    asm volatile("mma.sync.aligned.m16n8k16.row.col.f32.bf16.bf16.f32 "
                 "{%0,%1,%2,%3}, {%4,%5,%6,%7}, {%8,%9}, {%0,%1,%2,%3};"
                 : "+f"(d[0]), "+f"(d[1]), "+f"(d[2]), "+f"(d[3])
                 : "r"(a[0]), "r"(a[1]), "r"(a[2]), "r"(a[3]), "r"(b0), "r"(b1));
}
__device__ __forceinline__ void bf16_split(float v, bf16* hi, bf16* lo, size_t idx) {
    bf16 h = __float2bfloat16(v);
    hi[idx] = h;
    lo[idx] = __float2bfloat16(v - __bfloat162float(h));
}
__device__ __forceinline__ uint32_t packbf(float a, float b) {
    __nv_bfloat162 t = __floats2bfloat162_rn(a, b);
    return *(uint32_t*)&t;
}
__device__ __forceinline__ void bf16_split2(float v0, float v1, bf16* hi, bf16* lo, size_t off) {
    bf16 h0 = __float2bfloat16(v0), h1 = __float2bfloat16(v1);
    *(uint32_t*)(hi + off) = packbf(v0, v1);
    *(uint32_t*)(lo + off) = packbf(v0 - __bfloat162float(h0), v1 - __bfloat162float(h1));
}
__device__ __forceinline__ uint32_t swz(int r, int c) {
    return (uint32_t)(r * 64 + ((c ^ ((r >> 1) & 3)) << 4));
}
#define SWZ128(r, c8) ((uint32_t)((r)*128 + (((c8) ^ ((r)&7)) << 4)))

// ---------------- mma.sync GEMM ------------------------------------------------
// Flags: RED=emit GN partials; TOUT=transposed (B,DIM,T) output; GLUO=paired GLU
// output (weights row-interleaved a/g; writes a*sigmoid(g), N/2 wide).
template<int BM>
__device__ __forceinline__ void stage_load2(
    uint32_t stg,
    const bf16* __restrict__ Ahi, const bf16* __restrict__ Alo,
    const bf16* __restrict__ Bhi, const bf16* __restrict__ Blo,
    int m0, int n0, int K, int kc, int tid)
{
    constexpr int ACH = BM * 4;
    constexpr int TC = 2 * ACH + 2 * 512;
    constexpr int ITER = TC / 256;
#pragma unroll
    for (int it = 0; it < ITER; it++) {
        int idx = it * 256 + tid;
        const bf16* base; int r, c; uint32_t moff; int grow;
        if (idx < 2 * ACH) {
            int mat = idx / ACH;
            int e = idx - mat * ACH;
            r = e >> 2; c = e & 3;
            base = mat ? Alo : Ahi;
            grow = m0 + r;
            moff = (uint32_t)mat * (BM * 64);
        } else {
            int e2 = idx - 2 * ACH;
            int mat = e2 >> 9;
            int e = e2 & 511;
            r = e >> 2; c = e & 3;
            base = mat ? Blo : Bhi;
            grow = n0 + r;
            moff = 2 * (BM * 64) + (uint32_t)mat * 8192;
        }
        cp16(stg + moff + swz(r, c), base + (size_t)grow * K + kc * 32 + c * 8);
    }
}

template<int BM, bool GELU, bool RED, bool TOUT, bool GLUO>
__global__ void __launch_bounds__(256, 2) gemm_mma(
    const bf16* __restrict__ Ahi, const bf16* __restrict__ Alo,
    const bf16* __restrict__ Bhi, const bf16* __restrict__ Blo,
    const float* __restrict__ bias, const float* __restrict__ resid,
    float* __restrict__ C, bf16* __restrict__ Chi, bf16* __restrict__ Clo,
    int M, int N, int K, float alpha)
{
    constexpr int NW_N = (BM == 128) ? 2 : 4;
    constexpr int NT8  = (BM == 128) ? 8 : 4;
    constexpr int NBF  = NT8 / 2;
    constexpr int A_BYTES = BM * 64;
    constexpr int STG = 2 * A_BYTES + 2 * 8192;

    extern __shared__ char sm[];
    float* bias_s = (float*)sm;
    uint32_t tiles = smem_to_u32(sm) + 512;
    int tid = threadIdx.x, wid = tid >> 5, lane = tid & 31;
    int n0 = blockIdx.x * 128, m0 = blockIdx.y * BM;
    int wm = wid / NW_N, wn = wid % NW_N;

    if (tid < 128) {
        if (GLUO) {
            int n = n0 + tid;
            bias_s[tid] = bias[(n & 1) ? (512 + (n >> 1)) : (n >> 1)];
        } else {
            bias_s[tid] = bias[n0 + tid];
        }
    }

    float acc[2][NT8][4];
#pragma unroll
    for (int i = 0; i < 2; i++)
#pragma unroll
        for (int j = 0; j < NT8; j++)
#pragma unroll
            for (int q = 0; q < 4; q++) acc[i][j][q] = 0.f;

    const int nk = K >> 5;
    stage_load2<BM>(tiles + 0 * STG, Ahi, Alo, Bhi, Blo, m0, n0, K, 0, tid);
    CP_COMMIT();
    stage_load2<BM>(tiles + 1 * STG, Ahi, Alo, Bhi, Blo, m0, n0, K, 1, tid);
    CP_COMMIT();

    int rowA = wm * 32 + (lane & 15);
    int rowB = wn * (NBF * 16) + (lane & 15);
    int csel = lane >> 4;

    int slot = 0;
    for (int kc = 0; kc < nk; kc++) {
        CP_WAIT1();
        __syncthreads();
        if (kc + 2 < nk) {
            int ns = slot + 2; if (ns >= 3) ns -= 3;
            stage_load2<BM>(tiles + ns * STG, Ahi, Alo, Bhi, Blo, m0, n0, K, kc + 2, tid);
            CP_COMMIT();
        }
        uint32_t stg = tiles + slot * STG;
#pragma unroll
        for (int kk = 0; kk < 2; kk++) {
            int chunk = kk * 2 + csel;
            uint32_t af[2][4], bh[NBF][4], bl[NBF][4];
#pragma unroll
            for (int mt = 0; mt < 2; mt++) {
                int r = rowA + mt * 16;
                ldsm4(af[mt][0], af[mt][1], af[mt][2], af[mt][3], stg + swz(r, chunk));
            }
#pragma unroll
            for (int nt = 0; nt < NBF; nt++) {
                int r = rowB + nt * 16;
                ldsm4(bh[nt][0], bh[nt][1], bh[nt][2], bh[nt][3], stg + 2 * A_BYTES + swz(r, chunk));
                ldsm4(bl[nt][0], bl[nt][1], bl[nt][2], bl[nt][3], stg + 2 * A_BYTES + 8192 + swz(r, chunk));
            }
#pragma unroll
            for (int mt = 0; mt < 2; mt++)
#pragma unroll
                for (int nt8 = 0; nt8 < NT8; nt8++) {
                    int g = nt8 >> 1, s = nt8 & 1;
                    mma16816(acc[mt][nt8], af[mt], bh[g][s], bh[g][s + 2]);
                    mma16816(acc[mt][nt8], af[mt], bl[g][s], bl[g][s + 2]);
                }
#pragma unroll
            for (int mt = 0; mt < 2; mt++) {
                int r = rowA + mt * 16;
                ldsm4(af[mt][0], af[mt][1], af[mt][2], af[mt][3], stg + A_BYTES + swz(r, chunk));
            }
#pragma unroll
            for (int mt = 0; mt < 2; mt++)
#pragma unroll
                for (int nt8 = 0; nt8 < NT8; nt8++) {
                    int g = nt8 >> 1, s = nt8 & 1;
                    mma16816(acc[mt][nt8], af[mt], bh[g][s], bh[g][s + 2]);
                }
        }
        slot++; if (slot >= 3) slot = 0;
    }

    float* ot = (float*)(sm + 512);
    if (TOUT) __syncthreads();

    double su = 0.0, sq = 0.0;
    int rm = lane >> 2, cp = (lane & 3) * 2;
#pragma unroll
    for (int mt = 0; mt < 2; mt++) {
#pragma unroll
        for (int half = 0; half < 2; half++) {
            int mloc = wm * 32 + mt * 16 + half * 8 + rm;
            int m = m0 + mloc;
#pragma unroll
            for (int nt8 = 0; nt8 < NT8; nt8++) {
                int nl = wn * (NT8 * 8) + nt8 * 8 + cp;
                size_t off = (size_t)m * N + n0 + nl;
                float v0 = acc[mt][nt8][half * 2 + 0] + bias_s[nl];
                float v1 = acc[mt][nt8][half * 2 + 1] + bias_s[nl + 1];
                if (GELU) {
                    v0 = 0.5f * v0 * (1.0f + erff(v0 * 0.70710678f));
                    v1 = 0.5f * v1 * (1.0f + erff(v1 * 0.70710678f));
                }
                v0 *= alpha; v1 *= alpha;
                if (resid) {
                    float2 r = *(const float2*)(resid + off);
                    v0 += r.x; v1 += r.y;
                }
                if (GLUO) {
                    // v0 = a, v1 = g; output a*sigmoid(g) at col (n0+nl)/2
                    float glu = v0 / (1.f + expf(-v1));
                    C[(size_t)m * (N >> 1) + ((n0 + nl) >> 1)] = glu;
                } else if (TOUT) {
                    ot[mloc * 129 + nl] = v0;
                    ot[mloc * 129 + nl + 1] = v1;
                } else {
                    if (C) *(float2*)(C + off) = make_float2(v0, v1);
                    if (Chi) bf16_split2(v0, v1, Chi, Clo, off);
                }
                if (RED) {
                    su += (double)v0 + (double)v1;
                    sq += (double)v0 * v0 + (double)v1 * v1;
                }
            }
        }
    }
    if (TOUT) {
        __syncthreads();
        int bb = m0 >> 10, tt0 = m0 & 1023;
#pragma unroll
        for (int i = 0; i < 32; i++) {
            int idx = i * 256 + tid;
            int nl = idx >> 6, tl = idx & 63;
            C[((size_t)(bb * DIM_ + n0 + nl)) * T_ + tt0 + tl] = ot[tl * 129 + nl];
        }
    }
    if (RED) {
        __syncthreads();
        double* rs = (double*)(sm + 512);
        rs[tid] = su; rs[256 + tid] = sq;
        __syncthreads();
        for (int st = 128; st > 0; st >>= 1) {
            if (tid < st) {
                rs[tid] += rs[tid + st];
                rs[256 + tid] += rs[256 + tid + st];
            }
            __syncthreads();
        }
        if (tid == 0) {
            int bb = m0 >> 10;
            int tidx = ((blockIdx.y & 15)) * gridDim.x + blockIdx.x;
            g_PART[(bb * 128 + tidx) * 2 + 0] = rs[0];
            g_PART[(bb * 128 + tidx) * 2 + 1] = rs[256];
        }
    }
}

// ---------------- fused weight split ---------------------------------------------
__device__ void do_split_t(float (*t)[33], const float* __restrict__ W, bf16* hi, bf16* lo,
                           int K, int N, int tile) {
    int kt = K / 32;
    int k0 = (tile % kt) * 32, n0 = (tile / kt) * 32;
    int tx = threadIdx.x & 31, ty = threadIdx.x >> 5;
    for (int r = ty; r < 32; r += 8)
        t[r][tx] = W[(size_t)(k0 + r) * N + n0 + tx];
    __syncthreads();
    int tx2 = threadIdx.x & 15, ty2 = threadIdx.x >> 4;
    for (int rr = ty2; rr < 32; rr += 16)
        bf16_split2(t[2*tx2][rr], t[2*tx2+1][rr], hi, lo, (size_t)(n0 + rr) * K + k0 + 2*tx2);
}
__device__ void do_split_d(const float* __restrict__ W, bf16* hi, bf16* lo, int tile) {
    int i = tile * 1024 + threadIdx.x * 4;
    float4 v = *(const float4*)(W + i);
    bf16_split2(v.x, v.y, hi, lo, i);
    bf16_split2(v.z, v.w, hi, lo, i + 2);
}
// pw1: interleave rows so dst row 2j = a_j (src j), 2j+1 = g_j (src 512+j)
__device__ void do_split_pw1(const float* __restrict__ W, bf16* hi, bf16* lo, int tile) {
    int i = tile * 1024 + threadIdx.x * 4;     // source index; row-major (1024,512)
    int row = i >> 9, col = i & 511;
    int drow = (row < 512) ? (row * 2) : ((row - 512) * 2 + 1);
    size_t di = (size_t)drow * 512 + col;
    float4 v = *(const float4*)(W + i);
    bf16_split2(v.x, v.y, hi, lo, di);
    bf16_split2(v.z, v.w, hi, lo, di + 2);
}
__global__ void wsplit_all(const float* ff1_w1, const float* ff1_w2, const float* qkv_w,
                           const float* out_w, const float* pw1_w, const float* pw2_w,
                           const float* ff2_w1, const float* ff2_w2) {
    __shared__ float t[32][33];
    int b = blockIdx.x;
    if      (b < 1024) do_split_t(t, ff1_w1, g_Wf1a_hi, g_Wf1a_lo, DIM_, FF_, b);
    else if (b < 2048) do_split_t(t, ff1_w2, g_Wf1b_hi, g_Wf1b_lo, FF_, DIM_, b - 1024);
    else if (b < 2816) do_split_t(t, qkv_w,  g_Wqkv_hi, g_Wqkv_lo, DIM_, 1536, b - 2048);
    else if (b < 3072) do_split_t(t, out_w,  g_Wout_hi, g_Wout_lo, DIM_, DIM_, b - 2816);
    else if (b < 3584) do_split_pw1(pw1_w, g_Wpw1_hi, g_Wpw1_lo, b - 3072);
    else if (b < 3840) do_split_d(pw2_w, g_Wpw2_hi, g_Wpw2_lo, b - 3584);
    else if (b < 4864) do_split_t(t, ff2_w1, g_Wf2a_hi, g_Wf2a_lo, DIM_, FF_, b - 3840);
    else               do_split_t(t, ff2_w2, g_Wf2b_hi, g_Wf2b_lo, FF_, DIM_, b - 4864);
}

// ---------------- input transpose -----------------------------------------------
__global__ void transpose_bdt_to_btd(const float* __restrict__ in, float* __restrict__ out,
                                     bf16* __restrict__ ohi, bf16* __restrict__ olo) {
    __shared__ float tile[32][33];
    int b = blockIdx.z;
    int t0 = blockIdx.x * 32, d0 = blockIdx.y * 32;
    for (int i = threadIdx.y; i < 32; i += 8)
        tile[i][threadIdx.x] = in[((size_t)b*DIM_ + d0 + i)*T_ + t0 + threadIdx.x];
    __syncthreads();
    int tid = threadIdx.y * 32 + threadIdx.x;
    int dx = (tid & 15) * 2;
    int r0 = tid >> 4;
#pragma unroll
    for (int rstep = 0; rstep < 2; rstep++) {
        int i = r0 + rstep * 16;
        float v0 = tile[dx][i], v1 = tile[dx + 1][i];
        size_t o = ((size_t)b*T_ + t0 + i)*DIM_ + d0 + dx;
        *(float2*)(out + o) = make_float2(v0, v1);
        bf16_split2(v0, v1, ohi, olo, o);
    }
}

// ---------------- rel-bias table + gates ----------------------------------------
__global__ void rel_table_kernel(const float* __restrict__ rel_embed, float* __restrict__ tab) {
    int idx = blockIdx.x * 256 + threadIdx.x;
    if (idx >= 2047 * H_) return;
    int rr = idx >> 3, h = idx & 7;
    int rel = rr - 1023;
    int sign = (rel >= 0) ? 1 : 0;
    int ap = rel >= 0 ? rel : -rel;
    int bidx;
    if (ap < 80) bidx = ap;
    else {
        float lr = logf((float)ap / 80.0f) / 2.3025851f;
        int lp = (int)(80.0f + lr * 80.0f);
        bidx = lp < 159 ? lp : 159;
    }
    int bucket = bidx + sign * 160;
    bucket = bucket < 0 ? 0 : (bucket > 319 ? 319 : bucket);
    tab[h * 2048 + rr] = rel_embed[bucket * H_ + h];
}
__global__ void gates_kernel(const float* __restrict__ QKV, const float* __restrict__ gu,
                             const float* __restrict__ gw, const float* __restrict__ sh,
                             float* __restrict__ F) {
    int row = blockIdx.x * 8 + (threadIdx.x >> 5);
    int lane = threadIdx.x & 31;
    int t = row & (T_-1);
    int bh = row >> 10;
    int h = bh & (H_-1), b = bh >> 3;
    const float* q = QKV + ((size_t)(b*T_ + t))*1536 + h*DH_;
    float su = 0.f, sw = 0.f;
    for (int d = lane; d < DH_; d += 32) {
        float qv = q[d];
        su += qv * gu[h*DH_ + d];
        sw += qv * gw[h*DH_ + d];
    }
#pragma unroll
    for (int m = 16; m; m >>= 1) {
        su += __shfl_xor_sync(0xffffffff, su, m);
        sw += __shfl_xor_sync(0xffffffff, sw, m);
    }
    if (lane == 0) {
        float g_u = 1.f / (1.f + expf(-su));
        float g_w = 1.f / (1.f + expf(-sw));
        F[row] = 1.f + g_u + (1.f - g_u) * sh[h] * g_w;
    }
}

// ---------------- flash attention on mma.sync -----------------------------------
#define AQHI 0
#define AQLO 16384
#define AKHI 32768
#define AKLO 40960
#define AVTH 49152
#define AVTL 57344
#define AWOF 65536
#define ATTN_SMEM (65536 + 768)

__global__ void __launch_bounds__(256, 2) attn_mma(
    const float* __restrict__ QKV, const float* __restrict__ F,
    const float* __restrict__ TAB, bf16* __restrict__ Ohi, bf16* __restrict__ Olo)
{
    extern __shared__ char sma[];
    uint32_t sb = smem_to_u32(sma);
    float* Ws = (float*)(sma + AWOF);

    int tid = threadIdx.x, wid = tid >> 5, lane = tid & 31;
    int t0 = blockIdx.x * 128, h = blockIdx.y, b = blockIdx.z;

#pragma unroll
    for (int i = 0; i < 4; i++) {
        int task = i * 256 + tid;
        int r = task >> 3, c8 = task & 7;
        const float* src = QKV + ((size_t)(b*T_ + t0 + r))*1536 + h*64 + c8*8;
        float4 v0 = *(const float4*)src, v1 = *(const float4*)(src + 4);
        float vv[8] = {v0.x, v0.y, v0.z, v0.w, v1.x, v1.y, v1.z, v1.w};
        bf16 h8[8], l8[8];
#pragma unroll
        for (int j = 0; j < 8; j++) {
            h8[j] = __float2bfloat16(vv[j]);
            l8[j] = __float2bfloat16(vv[j] - __bfloat162float(h8[j]));
        }
        uint32_t off = SWZ128(r, c8);
        *(uint4*)(sma + AQHI + off) = *(uint4*)h8;
        *(uint4*)(sma + AQLO + off) = *(uint4*)l8;
    }
    int rloc0 = wid * 16 + (lane >> 2);
    int cbase = (lane & 3) * 2;
    float f0 = F[((b*H_ + h) << 10) + t0 + rloc0];
    float f1 = F[((b*H_ + h) << 10) + t0 + rloc0 + 8];

    float m_run[2] = {-1e30f, -1e30f}, l_run[2] = {0.f, 0.f};
    float acc_o[8][4];
#pragma unroll
    for (int i = 0; i < 8; i++)
#pragma unroll
        for (int q = 0; q < 4; q++) acc_o[i][q] = 0.f;

    for (int st = 0; st < T_/64; st++) {
        int s0 = st * 64;
        __syncthreads();
#pragma unroll
        for (int i = 0; i < 2; i++) {
            int task = i * 256 + tid;
            int r = task >> 3, c8 = task & 7;
            const float* src = QKV + ((size_t)(b*T_ + s0 + r))*1536 + 512 + h*64 + c8*8;
            float4 v0 = *(const float4*)src, v1 = *(const float4*)(src + 4);
            float vv[8] = {v0.x, v0.y, v0.z, v0.w, v1.x, v1.y, v1.z, v1.w};
            bf16 h8[8], l8[8];
#pragma unroll
            for (int j = 0; j < 8; j++) {
                h8[j] = __float2bfloat16(vv[j]);
                l8[j] = __float2bfloat16(vv[j] - __bfloat162float(h8[j]));
            }
            uint32_t off = SWZ128(r, c8);
            *(uint4*)(sma + AKHI + off) = *(uint4*)h8;
            *(uint4*)(sma + AKLO + off) = *(uint4*)l8;
        }
        {
            int sp = (tid & 31) * 2;
            int dg = (tid >> 5) * 8;
            const float* src0 = QKV + ((size_t)(b*T_ + s0 + sp))*1536 + 1024 + h*64 + dg;
            const float* src1 = src0 + 1536;
            float4 a0 = *(const float4*)src0, a1 = *(const float4*)(src0 + 4);
            float4 b0 = *(const float4*)src1, b1 = *(const float4*)(src1 + 4);
            float r0v[8] = {a0.x, a0.y, a0.z, a0.w, a1.x, a1.y, a1.z, a1.w};
            float r1v[8] = {b0.x, b0.y, b0.z, b0.w, b1.x, b1.y, b1.z, b1.w};
#pragma unroll
            for (int j = 0; j < 8; j++) {
                int d = dg + j;
                uint32_t off = (uint32_t)(d*128 + ((((sp >> 3) ^ (d & 7))) << 4) + (sp & 7)*2);
                float v0 = r0v[j], v1 = r1v[j];
                bf16 h0 = __float2bfloat16(v0), h1 = __float2bfloat16(v1);
                *(uint32_t*)(sma + AVTH + off) = packbf(v0, v1);
                *(uint32_t*)(sma + AVTL + off) =
                    packbf(v0 - __bfloat162float(h0), v1 - __bfloat162float(h1));
            }
        }
        if (tid < 192) {
            int gidx = s0 - t0 + 896 + tid;
            gidx = gidx < 0 ? 0 : (gidx > 2046 ? 2046 : gidx);
            Ws[tid] = TAB[h*2048 + gidx];
        }
        __syncthreads();

        float acc_s[8][4];
#pragma unroll
        for (int i = 0; i < 8; i++)
#pragma unroll
            for (int q = 0; q < 4; q++) acc_s[i][q] = 0.f;
        int qr = wid * 16 + (lane & 15);
#pragma unroll
        for (int ks = 0; ks < 4; ks++) {
            int chunk = ks * 2 + (lane >> 4);
            uint32_t qa[4], kh[4][4], kl[4][4];
            ldsm4(qa[0], qa[1], qa[2], qa[3], sb + AQHI + SWZ128(qr, chunk));
#pragma unroll
            for (int nt = 0; nt < 4; nt++) {
                int kr = nt * 16 + (lane & 15);
                ldsm4(kh[nt][0], kh[nt][1], kh[nt][2], kh[nt][3], sb + AKHI + SWZ128(kr, chunk));
                ldsm4(kl[nt][0], kl[nt][1], kl[nt][2], kl[nt][3], sb + AKLO + SWZ128(kr, chunk));
            }
#pragma unroll
            for (int nt8 = 0; nt8 < 8; nt8++) {
                int g = nt8 >> 1, s8 = nt8 & 1;
                mma16816(acc_s[nt8], qa, kh[g][s8], kh[g][s8 + 2]);
                mma16816(acc_s[nt8], qa, kl[g][s8], kl[g][s8 + 2]);
            }
            ldsm4(qa[0], qa[1], qa[2], qa[3], sb + AQLO + SWZ128(qr, chunk));
#pragma unroll
            for (int nt8 = 0; nt8 < 8; nt8++) {
                int g = nt8 >> 1, s8 = nt8 & 1;
                mma16816(acc_s[nt8], qa, kh[g][s8], kh[g][s8 + 2]);
            }
        }

#pragma unroll
        for (int h2 = 0; h2 < 2; h2++) {
            int rl = rloc0 + h2 * 8;
            float fv = h2 ? f1 : f0;
            float vmax = -1e30f;
#pragma unroll
            for (int nt = 0; nt < 8; nt++)
#pragma unroll
                for (int q = 0; q < 2; q++) {
                    int c = nt * 8 + cbase + q;
                    float sv = acc_s[nt][h2*2 + q] * 0.125f + fv * Ws[c - rl + 127];
                    acc_s[nt][h2*2 + q] = sv;
                    vmax = fmaxf(vmax, sv);
                }
            vmax = fmaxf(vmax, __shfl_xor_sync(0xffffffff, vmax, 1));
            vmax = fmaxf(vmax, __shfl_xor_sync(0xffffffff, vmax, 2));
            float mn = fmaxf(m_run[h2], vmax);
            float alpha = __expf(m_run[h2] - mn);
            m_run[h2] = mn;
            float rs = 0.f;
#pragma unroll
            for (int nt = 0; nt < 8; nt++)
#pragma unroll
                for (int q = 0; q < 2; q++) {
                    float p = __expf(acc_s[nt][h2*2 + q] - mn);
                    acc_s[nt][h2*2 + q] = p;
                    rs += p;
                }
            rs += __shfl_xor_sync(0xffffffff, rs, 1);
            rs += __shfl_xor_sync(0xffffffff, rs, 2);
            l_run[h2] = l_run[h2] * alpha + rs;
#pragma unroll
            for (int nt8 = 0; nt8 < 8; nt8++) {
                acc_o[nt8][h2*2 + 0] *= alpha;
                acc_o[nt8][h2*2 + 1] *= alpha;
            }
        }

#pragma unroll
        for (int kg = 0; kg < 4; kg++) {
            uint32_t ph[4], pl[4];
#pragma unroll
            for (int part = 0; part < 4; part++) {
                int tile = 2 * kg + (part >> 1);
                int o0 = (part & 1) * 2;
                float v0 = acc_s[tile][o0], v1 = acc_s[tile][o0 + 1];
                bf16 b0 = __float2bfloat16(v0), b1 = __float2bfloat16(v1);
                ph[part] = packbf(v0, v1);
                pl[part] = packbf(v0 - __bfloat162float(b0), v1 - __bfloat162float(b1));
            }
            int chunk = kg * 2 + (lane >> 4);
            uint32_t vh[4][4], vl[4][4];
#pragma unroll
            for (int ndt = 0; ndt < 4; ndt++) {
                int vr = ndt * 16 + (lane & 15);
                ldsm4(vh[ndt][0], vh[ndt][1], vh[ndt][2], vh[ndt][3], sb + AVTH + SWZ128(vr, chunk));
                ldsm4(vl[ndt][0], vl[ndt][1], vl[ndt][2], vl[ndt][3], sb + AVTL + SWZ128(vr, chunk));
            }
#pragma unroll
            for (int nd8 = 0; nd8 < 8; nd8++) {
                int g = nd8 >> 1, s8 = nd8 & 1;
                mma16816(acc_o[nd8], ph, vh[g][s8], vh[g][s8 + 2]);
                mma16816(acc_o[nd8], ph, vl[g][s8], vl[g][s8 + 2]);
                mma16816(acc_o[nd8], pl, vh[g][s8], vh[g][s8 + 2]);
            }
        }
    }

#pragma unroll
    for (int h2 = 0; h2 < 2; h2++) {
        float inv = 1.f / l_run[h2];
        int rg = t0 + rloc0 + h2 * 8;
#pragma unroll
        for (int nt8 = 0; nt8 < 8; nt8++) {
            int c = nt8 * 8 + cbase;
            float v0 = acc_o[nt8][h2*2 + 0] * inv;
            float v1 = acc_o[nt8][h2*2 + 1] * inv;
            size_t off = ((size_t)(b*T_ + rg))*DIM_ + h*64 + c;
            bf16_split2(v0, v1, Ohi, Olo, off);
        }
    }
}

// ---------------- GroupNorm finalize + apply ------------------------------------
__global__ void gn_finalize(int n) {
    int b = blockIdx.x;
    __shared__ double s1[128], s2[128];
    if (threadIdx.x < n) {
        s1[threadIdx.x] = g_PART[(b*128 + threadIdx.x)*2 + 0];
        s2[threadIdx.x] = g_PART[(b*128 + threadIdx.x)*2 + 1];
    }
    __syncthreads();
    if (threadIdx.x == 0) {
        double su = 0.0, sq = 0.0;
        for (int i = 0; i < n; i++) { su += s1[i]; sq += s2[i]; }
        double mean = su / (double)(T_*DIM_);
        double var = sq / (double)(T_*DIM_) - mean*mean;
        float inv = (float)(1.0 / sqrt(var + 1e-5));
        g_STATS[b] = make_float2((float)mean, inv);
    }
}
template<bool SILU>
__global__ void gn_apply(const float* __restrict__ x, const float* __restrict__ g,
                         const float* __restrict__ bt,
                         bf16* __restrict__ ohi, bf16* __restrict__ olo) {
    int idx = (blockIdx.x * 256 + threadIdx.x) * 2;
    int b = idx >> 19;
    int d = idx & (DIM_-1);
    float2 st = g_STATS[b];
    float2 xv = *(const float2*)(x + idx);
    float v0 = (xv.x - st.x) * st.y * g[d]     + bt[d];
    float v1 = (xv.y - st.x) * st.y * g[d + 1] + bt[d + 1];
    if (SILU) {
        v0 = v0 / (1.f + expf(-v0));
        v1 = v1 / (1.f + expf(-v1));
    }
    bf16_split2(v0, v1, ohi, olo, idx);
}

// ---------------- depthwise conv (GLU already applied) + GN partials ------------
__global__ void __launch_bounds__(256) dwconv_red(
    const float* __restrict__ gluin, const float* __restrict__ w,
    const float* __restrict__ wb, float* __restrict__ out)
{
    __shared__ float smv[94][64];
    __shared__ float smw[64][33];
    __shared__ double rsum[256], rsq[256];
    int b = blockIdx.z, t0 = blockIdx.x * 64, d0 = blockIdx.y * 64;
    int tid = threadIdx.x;
    for (int i = tid; i < 64 * KW; i += 256) {
        int dd = i / KW, j = i - dd * KW;
        smw[dd][j] = w[(size_t)(d0 + dd) * KW + j];
    }
    for (int i = tid; i < 94 * 64; i += 256) {
        int r = i >> 6, d = i & 63;
        int tt = t0 - 15 + r;
        float v = 0.f;
        if (tt >= 0 && tt < T_)
            v = gluin[((size_t)(b*T_ + tt))*DIM_ + d0 + d];
        smv[r][d] = v;
    }
    __syncthreads();
    int d = tid & 63, tr = tid >> 6;
    float wr[KW];
#pragma unroll
    for (int j = 0; j < KW; j++) wr[j] = smw[d][j];
    float bias = wb[d0 + d];
    double su = 0.0, sq = 0.0;
#pragma unroll 4
    for (int i = 0; i < 16; i++) {
        int t = tr * 16 + i;
        float acc = bias;
#pragma unroll
        for (int j = 0; j < KW; j++) acc += wr[j] * smv[t + j][d];
        out[((size_t)(b*T_ + t0 + t))*DIM_ + d0 + d] = acc;
        su += acc; sq += (double)acc * acc;
    }
    rsum[tid] = su; rsq[tid] = sq;
    __syncthreads();
    for (int st = 128; st > 0; st >>= 1) {
        if (tid < st) { rsum[tid] += rsum[tid + st]; rsq[tid] += rsq[tid + st]; }
        __syncthreads();
    }
    if (tid == 0) {
        int tidx = blockIdx.x * 8 + blockIdx.y;
        g_PART[(b*128 + tidx)*2 + 0] = rsum[0];
        g_PART[(b*128 + tidx)*2 + 1] = rsq[0];
    }
}

// ---------------- host ----------------------------------------------------------
static float* sym_f(const void* s) { void* p = nullptr; cudaGetSymbolAddress(&p, s); return (float*)p; }
static bf16* sym_b(const void* s) { void* p = nullptr; cudaGetSymbolAddress(&p, s); return (bf16*)p; }

#define SMEM_128 (512 + 3*(2*128*64 + 2*8192))
#define SMEM_64  (512 + 3*(2*64*64  + 2*8192))

extern "C" void kernel_launch(void* const* d_in, const int* in_sizes, int n_in,
                              void* d_out, int out_size) {
    const float* x      = (const float*)d_in[0];
    const float* ff1_w1 = (const float*)d_in[1];
    const float* ff1_b1 = (const float*)d_in[2];
    const float* ff1_w2 = (const float*)d_in[3];
    const float* ff1_b2 = (const float*)d_in[4];
    const float* qkv_w  = (const float*)d_in[5];
    const float* qkv_b  = (const float*)d_in[6];
    const float* out_w  = (const float*)d_in[7];
    const float* out_b  = (const float*)d_in[8];
    const float* gn1_g  = (const float*)d_in[9];
    const float* gn1_b  = (const float*)d_in[10];
    const float* pw1_w  = (const float*)d_in[11];
    const float* pw1_b  = (const float*)d_in[12];
    const float* dw_w   = (const float*)d_in[13];
    const float* dw_b   = (const float*)d_in[14];
    const float* gn2_g  = (const float*)d_in[15];
    const float* gn2_b  = (const float*)d_in[16];
    const float* pw2_w  = (const float*)d_in[17];
    const float* pw2_b  = (const float*)d_in[18];
    const float* ff2_w1 = (const float*)d_in[19];
    const float* ff2_b1 = (const float*)d_in[20];
    const float* ff2_w2 = (const float*)d_in[21];
    const float* ff2_b2 = (const float*)d_in[22];
    const float* rel_embed = (const float*)d_in[23];
    const float* gate_u = (const float*)d_in[24];
    const float* gate_w = (const float*)d_in[25];
    const float* scale_h = (const float*)d_in[26];

    float* S   = sym_f(g_S);
    float* T1  = sym_f(g_T1);
    float* QKV = sym_f(g_QKV);
    float* C1  = sym_f(g_C1);
    float* F   = sym_f(g_F);
    float* TAB = sym_f(g_TAB);
    bf16 *Shi = sym_b(g_Shi),  *Slo = sym_b(g_Slo);
    bf16 *Thi = sym_b(g_T1hi), *Tlo = sym_b(g_T1lo);
    bf16 *Ohi = sym_b(g_Ohi),  *Olo = sym_b(g_Olo);
    bf16 *Nhi = sym_b(g_N1hi), *Nlo = sym_b(g_N1lo);
    bf16 *Wf1a_hi = sym_b(g_Wf1a_hi), *Wf1a_lo = sym_b(g_Wf1a_lo);
    bf16 *Wf1b_hi = sym_b(g_Wf1b_hi), *Wf1b_lo = sym_b(g_Wf1b_lo);
    bf16 *Wqkv_hi = sym_b(g_Wqkv_hi), *Wqkv_lo = sym_b(g_Wqkv_lo);
    bf16 *Wout_hi = sym_b(g_Wout_hi), *Wout_lo = sym_b(g_Wout_lo);
    bf16 *Wpw1_hi = sym_b(g_Wpw1_hi), *Wpw1_lo = sym_b(g_Wpw1_lo);
    bf16 *Wpw2_hi = sym_b(g_Wpw2_hi), *Wpw2_lo = sym_b(g_Wpw2_lo);
    bf16 *Wf2a_hi = sym_b(g_Wf2a_hi), *Wf2a_lo = sym_b(g_Wf2a_lo);
    bf16 *Wf2b_hi = sym_b(g_Wf2b_hi), *Wf2b_lo = sym_b(g_Wf2b_lo);

    const int M = B_*T_;
    dim3 tb(32, 8);

    cudaFuncSetAttribute(gemm_mma<128,false,false,false,false>, cudaFuncAttributeMaxDynamicSharedMemorySize, SMEM_128);
    cudaFuncSetAttribute(gemm_mma<128,true,false,false,false>,  cudaFuncAttributeMaxDynamicSharedMemorySize, SMEM_128);
    cudaFuncSetAttribute(gemm_mma<128,false,false,false,true>,  cudaFuncAttributeMaxDynamicSharedMemorySize, SMEM_128);
    cudaFuncSetAttribute(gemm_mma<64,false,false,false,false>,  cudaFuncAttributeMaxDynamicSharedMemorySize, SMEM_64);
    cudaFuncSetAttribute(gemm_mma<64,false,true,false,false>,   cudaFuncAttributeMaxDynamicSharedMemorySize, SMEM_64);
    cudaFuncSetAttribute(gemm_mma<64,false,false,true,false>,   cudaFuncAttributeMaxDynamicSharedMemorySize, SMEM_64);
    cudaFuncSetAttribute(attn_mma, cudaFuncAttributeMaxDynamicSharedMemorySize, ATTN_SMEM);

    wsplit_all<<<5888, 256>>>(ff1_w1, ff1_w2, qkv_w, out_w, pw1_w, pw2_w, ff2_w1, ff2_w2);
    transpose_bdt_to_btd<<<dim3(T_/32, DIM_/32, B_), tb>>>(x, S, Shi, Slo);

    gemm_mma<128,true,false,false,false><<<dim3(FF_/128, M/128), 256, SMEM_128>>>(Shi, Slo, Wf1a_hi, Wf1a_lo, ff1_b1, nullptr, nullptr, Thi, Tlo, M, FF_, DIM_, 1.0f);
    gemm_mma<64,false,false,false,false><<<dim3(DIM_/128, M/64), 256, SMEM_64>>>(Thi, Tlo, Wf1b_hi, Wf1b_lo, ff1_b2, S, S, Shi, Slo, M, DIM_, FF_, 0.5f);
    gemm_mma<128,false,false,false,false><<<dim3(1536/128, M/128), 256, SMEM_128>>>(Shi, Slo, Wqkv_hi, Wqkv_lo, qkv_b, nullptr, QKV, nullptr, nullptr, M, 1536, DIM_, 1.0f);

    rel_table_kernel<<<(2047*H_ + 255)/256, 256>>>(rel_embed, TAB);
    gates_kernel<<<(B_*H_*T_)/8, 256>>>(QKV, gate_u, gate_w, scale_h, F);
    attn_mma<<<dim3(T_/128, H_, B_), 256, ATTN_SMEM>>>(QKV, F, TAB, Ohi, Olo);

    // out proj + residual; fused GN1 partials
    gemm_mma<64,false,true,false,false><<<dim3(DIM_/128, M/64), 256, SMEM_64>>>(Ohi, Olo, Wout_hi, Wout_lo, out_b, S, S, nullptr, nullptr, M, DIM_, DIM_, 1.0f);

    gn_finalize<<<B_, 64>>>(64);
    gn_apply<false><<<(B_*T_*DIM_)/512, 256>>>(S, gn1_g, gn1_b, Nhi, Nlo);

    // pw1 with interleaved weights + GLU epilogue -> C1 (4096 x 512 fp32)
    gemm_mma<128,false,false,false,true><<<dim3(1024/128, M/128), 256, SMEM_128>>>(Nhi, Nlo, Wpw1_hi, Wpw1_lo, pw1_b, nullptr, C1, nullptr, nullptr, M, 1024, DIM_, 1.0f);

    // depthwise conv on GLU output; GN2 partials; result -> T1
    dwconv_red<<<dim3(T_/64, DIM_/64, B_), 256>>>(C1, dw_w, dw_b, T1);

    gn_finalize<<<B_, 128>>>(128);
    gn_apply<true><<<(B_*T_*DIM_)/512, 256>>>(T1, gn2_g, gn2_b, Nhi, Nlo);

    gemm_mma<64,false,false,false,false><<<dim3(DIM_/128, M/64), 256, SMEM_64>>>(Nhi, Nlo, Wpw2_hi, Wpw2_lo, pw2_b, S, S, Shi, Slo, M, DIM_, DIM_, 1.0f);

    gemm_mma<128,true,false,false,false><<<dim3(FF_/128, M/128), 256, SMEM_128>>>(Shi, Slo, Wf2a_hi, Wf2a_lo, ff2_b1, nullptr, nullptr, Thi, Tlo, M, FF_, DIM_, 1.0f);
    // FF2b: direct transposed output
    gemm_mma<64,false,false,true,false><<<dim3(DIM_/128, M/64), 256, SMEM_64>>>(Thi, Tlo, Wf2b_hi, Wf2b_lo, ff2_b2, S, (float*)d_out, nullptr, nullptr, M, DIM_, FF_, 0.5f);
}

// round 16
// speedup vs baseline: 1.0259x; 1.0048x over previous
#include <cuda_runtime.h>
#include <cuda_bf16.h>
#include <math.h>
#include <stdint.h>

#define B_ 4
#define T_ 1024
#define DIM_ 512
#define H_ 8
#define DH_ 64
#define FF_ 2048
#define KW 31

typedef __nv_bfloat16 bf16;

// ---------------- scratch (device globals) ------------------------------------
__device__ float g_S  [B_*T_*DIM_];
__device__ float g_T1 [B_*T_*FF_];
__device__ float g_QKV[B_*T_*3*DIM_];
__device__ float g_C1 [B_*T_*DIM_];
__device__ float g_F  [B_*H_*T_];
__device__ float g_TAB[H_*2048];
__device__ double g_PART[B_*128*2];
__device__ float2 g_STATS[B_];
__device__ bf16 g_Shi[B_*T_*DIM_],  g_Slo[B_*T_*DIM_];
__device__ bf16 g_T1hi[B_*T_*FF_],  g_T1lo[B_*T_*FF_];
__device__ bf16 g_Ohi[B_*T_*DIM_],  g_Olo[B_*T_*DIM_];
__device__ bf16 g_N1hi[B_*T_*DIM_], g_N1lo[B_*T_*DIM_];
__device__ bf16 g_Wf1a_hi[FF_*DIM_],  g_Wf1a_lo[FF_*DIM_];
__device__ bf16 g_Wf1b_hi[DIM_*FF_],  g_Wf1b_lo[DIM_*FF_];
__device__ bf16 g_Wqkv_hi[1536*DIM_], g_Wqkv_lo[1536*DIM_];
__device__ bf16 g_Wout_hi[DIM_*DIM_], g_Wout_lo[DIM_*DIM_];
__device__ bf16 g_Wpw1_hi[1024*DIM_], g_Wpw1_lo[1024*DIM_];
__device__ bf16 g_Wpw2_hi[DIM_*DIM_], g_Wpw2_lo[DIM_*DIM_];
__device__ bf16 g_Wf2a_hi[FF_*DIM_],  g_Wf2a_lo[FF_*DIM_];
__device__ bf16 g_Wf2b_hi[DIM_*FF_],  g_Wf2b_lo[DIM_*FF_];

// ---------------- helpers ------------------------------------------------------
__device__ __forceinline__ uint32_t smem_to_u32(const void* p) {
    uint32_t a;
    asm("{ .reg .u64 t; cvta.to.shared.u64 t, %1; cvt.u32.u64 %0, t; }" : "=r"(a) : "l"(p));
    return a;
}
__device__ __forceinline__ void cp16(uint32_t dst, const void* src) {
    asm volatile("cp.async.cg.shared.global [%0], [%1], 16;" :: "r"(dst), "l"(src));
}
#define CP_COMMIT() asm volatile("cp.async.commit_group;" ::: "memory")
#define CP_WAIT1()  asm volatile("cp.async.wait_group 1;" ::: "memory")

__device__ __forceinline__ void ldsm4(uint32_t& r0, uint32_t& r1, uint32_t& r2, uint32_t& r3, uint32_t addr) {
    asm volatile("ldmatrix.sync.aligned.m8n8.x4.shared.b16 {%0,%1,%2,%3}, [%4];"
                 : "=r"(r0), "=r"(r1), "=r"(r2), "=r"(r3) : "r"(addr));
}
__device__ __forceinline__ void mma16816(float* d, const uint32_t* a, uint32_t b0, uint32_t b1) {
    asm volatile("mma.sync.aligned.m16n8k16.row.col.f32.bf16.bf16.f32 "
                 "{%0,%1,%2,%3}, {%4,%5,%6,%7}, {%8,%9}, {%0,%1,%2,%3};"
                 : "+f"(d[0]), "+f"(d[1]), "+f"(d[2]), "+f"(d[3])
                 : "r"(a[0]), "r"(a[1]), "r"(a[2]), "r"(a[3]), "r"(b0), "r"(b1));
}
__device__ __forceinline__ void bf16_split(float v, bf16* hi, bf16* lo, size_t idx) {
    bf16 h = __float2bfloat16(v);
    hi[idx] = h;
    lo[idx] = __float2bfloat16(v - __bfloat162float(h));
}
__device__ __forceinline__ uint32_t packbf(float a, float b) {
    __nv_bfloat162 t = __floats2bfloat162_rn(a, b);
    return *(uint32_t*)&t;
}
__device__ __forceinline__ void bf16_split2(float v0, float v1, bf16* hi, bf16* lo, size_t off) {
    bf16 h0 = __float2bfloat16(v0), h1 = __float2bfloat16(v1);
    *(uint32_t*)(hi + off) = packbf(v0, v1);
    *(uint32_t*)(lo + off) = packbf(v0 - __bfloat162float(h0), v1 - __bfloat162float(h1));
}
__device__ __forceinline__ uint32_t swz(int r, int c) {
    return (uint32_t)(r * 64 + ((c ^ ((r >> 1) & 3)) << 4));
}
#define SWZ128(r, c8) ((uint32_t)((r)*128 + (((c8) ^ ((r)&7)) << 4)))

// ---------------- mma.sync GEMM ------------------------------------------------
template<int BM>
__device__ __forceinline__ void stage_load2(
    uint32_t stg,
    const bf16* __restrict__ Ahi, const bf16* __restrict__ Alo,
    const bf16* __restrict__ Bhi, const bf16* __restrict__ Blo,
    int m0, int n0, int K, int kc, int tid)
{
    constexpr int ACH = BM * 4;
    constexpr int TC = 2 * ACH + 2 * 512;
    constexpr int ITER = TC / 256;
#pragma unroll
    for (int it = 0; it < ITER; it++) {
        int idx = it * 256 + tid;
        const bf16* base; int r, c; uint32_t moff; int grow;
        if (idx < 2 * ACH) {
            int mat = idx / ACH;
            int e = idx - mat * ACH;
            r = e >> 2; c = e & 3;
            base = mat ? Alo : Ahi;
            grow = m0 + r;
            moff = (uint32_t)mat * (BM * 64);
        } else {
            int e2 = idx - 2 * ACH;
            int mat = e2 >> 9;
            int e = e2 & 511;
            r = e >> 2; c = e & 3;
            base = mat ? Blo : Bhi;
            grow = n0 + r;
            moff = 2 * (BM * 64) + (uint32_t)mat * 8192;
        }
        cp16(stg + moff + swz(r, c), base + (size_t)grow * K + kc * 32 + c * 8);
    }
}

template<int BM, bool GELU, bool RED, bool TOUT, bool GLUO>
__global__ void __launch_bounds__(256, 2) gemm_mma(
    const bf16* __restrict__ Ahi, const bf16* __restrict__ Alo,
    const bf16* __restrict__ Bhi, const bf16* __restrict__ Blo,
    const float* __restrict__ bias, const float* __restrict__ resid,
    float* __restrict__ C, bf16* __restrict__ Chi, bf16* __restrict__ Clo,
    int M, int N, int K, float alpha)
{
    constexpr int NW_N = (BM == 128) ? 2 : 4;
    constexpr int NT8  = (BM == 128) ? 8 : 4;
    constexpr int NBF  = NT8 / 2;
    constexpr int A_BYTES = BM * 64;
    constexpr int STG = 2 * A_BYTES + 2 * 8192;

    extern __shared__ char sm[];
    float* bias_s = (float*)sm;
    uint32_t tiles = smem_to_u32(sm) + 512;
    int tid = threadIdx.x, wid = tid >> 5, lane = tid & 31;
    int n0 = blockIdx.x * 128, m0 = blockIdx.y * BM;
    int wm = wid / NW_N, wn = wid % NW_N;

    if (tid < 128) {
        if (GLUO) {
            int n = n0 + tid;
            bias_s[tid] = bias[(n & 1) ? (512 + (n >> 1)) : (n >> 1)];
        } else {
            bias_s[tid] = bias[n0 + tid];
        }
    }

    float acc[2][NT8][4];
#pragma unroll
    for (int i = 0; i < 2; i++)
#pragma unroll
        for (int j = 0; j < NT8; j++)
#pragma unroll
            for (int q = 0; q < 4; q++) acc[i][j][q] = 0.f;

    const int nk = K >> 5;
    stage_load2<BM>(tiles + 0 * STG, Ahi, Alo, Bhi, Blo, m0, n0, K, 0, tid);
    CP_COMMIT();
    stage_load2<BM>(tiles + 1 * STG, Ahi, Alo, Bhi, Blo, m0, n0, K, 1, tid);
    CP_COMMIT();

    int rowA = wm * 32 + (lane & 15);
    int rowB = wn * (NBF * 16) + (lane & 15);
    int csel = lane >> 4;

    int slot = 0;
    for (int kc = 0; kc < nk; kc++) {
        CP_WAIT1();
        __syncthreads();
        if (kc + 2 < nk) {
            int ns = slot + 2; if (ns >= 3) ns -= 3;
            stage_load2<BM>(tiles + ns * STG, Ahi, Alo, Bhi, Blo, m0, n0, K, kc + 2, tid);
            CP_COMMIT();
        }
        uint32_t stg = tiles + slot * STG;
#pragma unroll
        for (int kk = 0; kk < 2; kk++) {
            int chunk = kk * 2 + csel;
            uint32_t af[2][4], bh[NBF][4], bl[NBF][4];
#pragma unroll
            for (int mt = 0; mt < 2; mt++) {
                int r = rowA + mt * 16;
                ldsm4(af[mt][0], af[mt][1], af[mt][2], af[mt][3], stg + swz(r, chunk));
            }
#pragma unroll
            for (int nt = 0; nt < NBF; nt++) {
                int r = rowB + nt * 16;
                ldsm4(bh[nt][0], bh[nt][1], bh[nt][2], bh[nt][3], stg + 2 * A_BYTES + swz(r, chunk));
                ldsm4(bl[nt][0], bl[nt][1], bl[nt][2], bl[nt][3], stg + 2 * A_BYTES + 8192 + swz(r, chunk));
            }
#pragma unroll
            for (int mt = 0; mt < 2; mt++)
#pragma unroll
                for (int nt8 = 0; nt8 < NT8; nt8++) {
                    int g = nt8 >> 1, s = nt8 & 1;
                    mma16816(acc[mt][nt8], af[mt], bh[g][s], bh[g][s + 2]);
                    mma16816(acc[mt][nt8], af[mt], bl[g][s], bl[g][s + 2]);
                }
#pragma unroll
            for (int mt = 0; mt < 2; mt++) {
                int r = rowA + mt * 16;
                ldsm4(af[mt][0], af[mt][1], af[mt][2], af[mt][3], stg + A_BYTES + swz(r, chunk));
            }
#pragma unroll
            for (int mt = 0; mt < 2; mt++)
#pragma unroll
                for (int nt8 = 0; nt8 < NT8; nt8++) {
                    int g = nt8 >> 1, s = nt8 & 1;
                    mma16816(acc[mt][nt8], af[mt], bh[g][s], bh[g][s + 2]);
                }
        }
        slot++; if (slot >= 3) slot = 0;
    }

    float* ot = (float*)(sm + 512);
    if (TOUT) __syncthreads();

    double su = 0.0, sq = 0.0;
    int rm = lane >> 2, cp = (lane & 3) * 2;
#pragma unroll
    for (int mt = 0; mt < 2; mt++) {
#pragma unroll
        for (int half = 0; half < 2; half++) {
            int mloc = wm * 32 + mt * 16 + half * 8 + rm;
            int m = m0 + mloc;
#pragma unroll
            for (int nt8 = 0; nt8 < NT8; nt8++) {
                int nl = wn * (NT8 * 8) + nt8 * 8 + cp;
                size_t off = (size_t)m * N + n0 + nl;
                float v0 = acc[mt][nt8][half * 2 + 0] + bias_s[nl];
                float v1 = acc[mt][nt8][half * 2 + 1] + bias_s[nl + 1];
                if (GELU) {
                    v0 = 0.5f * v0 * (1.0f + erff(v0 * 0.70710678f));
                    v1 = 0.5f * v1 * (1.0f + erff(v1 * 0.70710678f));
                }
                v0 *= alpha; v1 *= alpha;
                if (resid) {
                    float2 r = *(const float2*)(resid + off);
                    v0 += r.x; v1 += r.y;
                }
                if (GLUO) {
                    float glu = v0 / (1.f + expf(-v1));
                    C[(size_t)m * (N >> 1) + ((n0 + nl) >> 1)] = glu;
                } else if (TOUT) {
                    ot[mloc * 129 + nl] = v0;
                    ot[mloc * 129 + nl + 1] = v1;
                } else {
                    if (C) *(float2*)(C + off) = make_float2(v0, v1);
                    if (Chi) bf16_split2(v0, v1, Chi, Clo, off);
                }
                if (RED) {
                    su += (double)v0 + (double)v1;
                    sq += (double)v0 * v0 + (double)v1 * v1;
                }
            }
        }
    }
    if (TOUT) {
        __syncthreads();
        int bb = m0 >> 10, tt0 = m0 & 1023;
#pragma unroll
        for (int i = 0; i < 32; i++) {
            int idx = i * 256 + tid;
            int nl = idx >> 6, tl = idx & 63;
            C[((size_t)(bb * DIM_ + n0 + nl)) * T_ + tt0 + tl] = ot[tl * 129 + nl];
        }
    }
    if (RED) {
        __syncthreads();
        double* rs = (double*)(sm + 512);
        rs[tid] = su; rs[256 + tid] = sq;
        __syncthreads();
        for (int st = 128; st > 0; st >>= 1) {
            if (tid < st) {
                rs[tid] += rs[tid + st];
                rs[256 + tid] += rs[256 + tid + st];
            }
            __syncthreads();
        }
        if (tid == 0) {
            int bb = m0 >> 10;
            int tidx = ((blockIdx.y & 15)) * gridDim.x + blockIdx.x;
            g_PART[(bb * 128 + tidx) * 2 + 0] = rs[0];
            g_PART[(bb * 128 + tidx) * 2 + 1] = rs[256];
        }
    }
}

// ---------------- merged prep: weight splits + rel table + input transpose ------
__device__ void do_split_t(float (*t)[33], const float* __restrict__ W, bf16* hi, bf16* lo,
                           int K, int N, int tile) {
    int kt = K / 32;
    int k0 = (tile % kt) * 32, n0 = (tile / kt) * 32;
    int tx = threadIdx.x & 31, ty = threadIdx.x >> 5;
    for (int r = ty; r < 32; r += 8)
        t[r][tx] = W[(size_t)(k0 + r) * N + n0 + tx];
    __syncthreads();
    int tx2 = threadIdx.x & 15, ty2 = threadIdx.x >> 4;
    for (int rr = ty2; rr < 32; rr += 16)
        bf16_split2(t[2*tx2][rr], t[2*tx2+1][rr], hi, lo, (size_t)(n0 + rr) * K + k0 + 2*tx2);
}
__device__ void do_split_d(const float* __restrict__ W, bf16* hi, bf16* lo, int tile) {
    int i = tile * 1024 + threadIdx.x * 4;
    float4 v = *(const float4*)(W + i);
    bf16_split2(v.x, v.y, hi, lo, i);
    bf16_split2(v.z, v.w, hi, lo, i + 2);
}
__device__ void do_split_pw1(const float* __restrict__ W, bf16* hi, bf16* lo, int tile) {
    int i = tile * 1024 + threadIdx.x * 4;
    int row = i >> 9, col = i & 511;
    int drow = (row < 512) ? (row * 2) : ((row - 512) * 2 + 1);
    size_t di = (size_t)drow * 512 + col;
    float4 v = *(const float4*)(W + i);
    bf16_split2(v.x, v.y, hi, lo, di);
    bf16_split2(v.z, v.w, hi, lo, di + 2);
}
__device__ void do_rel_table(const float* __restrict__ rel_embed, float* __restrict__ tab, int idx) {
    if (idx >= 2047 * H_) return;
    int rr = idx >> 3, h = idx & 7;
    int rel = rr - 1023;
    int sign = (rel >= 0) ? 1 : 0;
    int ap = rel >= 0 ? rel : -rel;
    int bidx;
    if (ap < 80) bidx = ap;
    else {
        float lr = logf((float)ap / 80.0f) / 2.3025851f;
        int lp = (int)(80.0f + lr * 80.0f);
        bidx = lp < 159 ? lp : 159;
    }
    int bucket = bidx + sign * 160;
    bucket = bucket < 0 ? 0 : (bucket > 319 ? 319 : bucket);
    tab[h * 2048 + rr] = rel_embed[bucket * H_ + h];
}
__device__ void do_transpose(float (*t)[33], const float* __restrict__ in, float* __restrict__ out,
                             bf16* __restrict__ ohi, bf16* __restrict__ olo, int tile) {
    int bz = tile >> 9;                 // / (32*16)
    int rem = tile & 511;
    int t0 = (rem & 31) * 32, d0 = (rem >> 5) * 32;
    int tx = threadIdx.x & 31, ty = threadIdx.x >> 5;
    for (int r = ty; r < 32; r += 8)
        t[r][tx] = in[((size_t)bz*DIM_ + d0 + r)*T_ + t0 + tx];
    __syncthreads();
    int tid = threadIdx.x;
    int dx = (tid & 15) * 2;
    int r0 = tid >> 4;
#pragma unroll
    for (int rstep = 0; rstep < 2; rstep++) {
        int i = r0 + rstep * 16;
        float v0 = t[dx][i], v1 = t[dx + 1][i];
        size_t o = ((size_t)bz*T_ + t0 + i)*DIM_ + d0 + dx;
        *(float2*)(out + o) = make_float2(v0, v1);
        bf16_split2(v0, v1, ohi, olo, o);
    }
}
__global__ void prep_all(const float* ff1_w1, const float* ff1_w2, const float* qkv_w,
                         const float* out_w, const float* pw1_w, const float* pw2_w,
                         const float* ff2_w1, const float* ff2_w2,
                         const float* rel_embed, const float* x,
                         float* S, bf16* Shi, bf16* Slo) {
    __shared__ float t[32][33];
    int b = blockIdx.x;
    if      (b < 1024) do_split_t(t, ff1_w1, g_Wf1a_hi, g_Wf1a_lo, DIM_, FF_, b);
    else if (b < 2048) do_split_t(t, ff1_w2, g_Wf1b_hi, g_Wf1b_lo, FF_, DIM_, b - 1024);
    else if (b < 2816) do_split_t(t, qkv_w,  g_Wqkv_hi, g_Wqkv_lo, DIM_, 1536, b - 2048);
    else if (b < 3072) do_split_t(t, out_w,  g_Wout_hi, g_Wout_lo, DIM_, DIM_, b - 2816);
    else if (b < 3584) do_split_pw1(pw1_w, g_Wpw1_hi, g_Wpw1_lo, b - 3072);
    else if (b < 3840) do_split_d(pw2_w, g_Wpw2_hi, g_Wpw2_lo, b - 3584);
    else if (b < 4864) do_split_t(t, ff2_w1, g_Wf2a_hi, g_Wf2a_lo, DIM_, FF_, b - 3840);
    else if (b < 5888) do_split_t(t, ff2_w2, g_Wf2b_hi, g_Wf2b_lo, FF_, DIM_, b - 4864);
    else if (b < 5952) do_rel_table(rel_embed, g_TAB, (b - 5888) * 256 + threadIdx.x);
    else               do_transpose(t, x, S, Shi, Slo, b - 5952);
}

// ---------------- gates ---------------------------------------------------------
__global__ void gates_kernel(const float* __restrict__ QKV, const float* __restrict__ gu,
                             const float* __restrict__ gw, const float* __restrict__ sh,
                             float* __restrict__ F) {
    int row = blockIdx.x * 8 + (threadIdx.x >> 5);
    int lane = threadIdx.x & 31;
    int t = row & (T_-1);
    int bh = row >> 10;
    int h = bh & (H_-1), b = bh >> 3;
    const float* q = QKV + ((size_t)(b*T_ + t))*1536 + h*DH_;
    float su = 0.f, sw = 0.f;
    for (int d = lane; d < DH_; d += 32) {
        float qv = q[d];
        su += qv * gu[h*DH_ + d];
        sw += qv * gw[h*DH_ + d];
    }
#pragma unroll
    for (int m = 16; m; m >>= 1) {
        su += __shfl_xor_sync(0xffffffff, su, m);
        sw += __shfl_xor_sync(0xffffffff, sw, m);
    }
    if (lane == 0) {
        float g_u = 1.f / (1.f + expf(-su));
        float g_w = 1.f / (1.f + expf(-sw));
        F[row] = 1.f + g_u + (1.f - g_u) * sh[h] * g_w;
    }
}

// ---------------- flash attention on mma.sync -----------------------------------
#define AQHI 0
#define AQLO 16384
#define AKHI 32768
#define AKLO 40960
#define AVTH 49152
#define AVTL 57344
#define AWOF 65536
#define ATTN_SMEM (65536 + 768)

__global__ void __launch_bounds__(256, 2) attn_mma(
    const float* __restrict__ QKV, const float* __restrict__ F,
    const float* __restrict__ TAB, bf16* __restrict__ Ohi, bf16* __restrict__ Olo)
{
    extern __shared__ char sma[];
    uint32_t sb = smem_to_u32(sma);
    float* Ws = (float*)(sma + AWOF);

    int tid = threadIdx.x, wid = tid >> 5, lane = tid & 31;
    int t0 = blockIdx.x * 128, h = blockIdx.y, b = blockIdx.z;

#pragma unroll
    for (int i = 0; i < 4; i++) {
        int task = i * 256 + tid;
        int r = task >> 3, c8 = task & 7;
        const float* src = QKV + ((size_t)(b*T_ + t0 + r))*1536 + h*64 + c8*8;
        float4 v0 = *(const float4*)src, v1 = *(const float4*)(src + 4);
        float vv[8] = {v0.x, v0.y, v0.z, v0.w, v1.x, v1.y, v1.z, v1.w};
        bf16 h8[8], l8[8];
#pragma unroll
        for (int j = 0; j < 8; j++) {
            h8[j] = __float2bfloat16(vv[j]);
            l8[j] = __float2bfloat16(vv[j] - __bfloat162float(h8[j]));
        }
        uint32_t off = SWZ128(r, c8);
        *(uint4*)(sma + AQHI + off) = *(uint4*)h8;
        *(uint4*)(sma + AQLO + off) = *(uint4*)l8;
    }
    int rloc0 = wid * 16 + (lane >> 2);
    int cbase = (lane & 3) * 2;
    float f0 = F[((b*H_ + h) << 10) + t0 + rloc0];
    float f1 = F[((b*H_ + h) << 10) + t0 + rloc0 + 8];

    float m_run[2] = {-1e30f, -1e30f}, l_run[2] = {0.f, 0.f};
    float acc_o[8][4];
#pragma unroll
    for (int i = 0; i < 8; i++)
#pragma unroll
        for (int q = 0; q < 4; q++) acc_o[i][q] = 0.f;

    for (int st = 0; st < T_/64; st++) {
        int s0 = st * 64;
        __syncthreads();
#pragma unroll
        for (int i = 0; i < 2; i++) {
            int task = i * 256 + tid;
            int r = task >> 3, c8 = task & 7;
            const float* src = QKV + ((size_t)(b*T_ + s0 + r))*1536 + 512 + h*64 + c8*8;
            float4 v0 = *(const float4*)src, v1 = *(const float4*)(src + 4);
            float vv[8] = {v0.x, v0.y, v0.z, v0.w, v1.x, v1.y, v1.z, v1.w};
            bf16 h8[8], l8[8];
#pragma unroll
            for (int j = 0; j < 8; j++) {
                h8[j] = __float2bfloat16(vv[j]);
                l8[j] = __float2bfloat16(vv[j] - __bfloat162float(h8[j]));
            }
            uint32_t off = SWZ128(r, c8);
            *(uint4*)(sma + AKHI + off) = *(uint4*)h8;
            *(uint4*)(sma + AKLO + off) = *(uint4*)l8;
        }
        {
            int sp = (tid & 31) * 2;
            int dg = (tid >> 5) * 8;
            const float* src0 = QKV + ((size_t)(b*T_ + s0 + sp))*1536 + 1024 + h*64 + dg;
            const float* src1 = src0 + 1536;
            float4 a0 = *(const float4*)src0, a1 = *(const float4*)(src0 + 4);
            float4 b0 = *(const float4*)src1, b1 = *(const float4*)(src1 + 4);
            float r0v[8] = {a0.x, a0.y, a0.z, a0.w, a1.x, a1.y, a1.z, a1.w};
            float r1v[8] = {b0.x, b0.y, b0.z, b0.w, b1.x, b1.y, b1.z, b1.w};
#pragma unroll
            for (int j = 0; j < 8; j++) {
                int d = dg + j;
                uint32_t off = (uint32_t)(d*128 + ((((sp >> 3) ^ (d & 7))) << 4) + (sp & 7)*2);
                float v0 = r0v[j], v1 = r1v[j];
                bf16 h0 = __float2bfloat16(v0), h1 = __float2bfloat16(v1);
                *(uint32_t*)(sma + AVTH + off) = packbf(v0, v1);
                *(uint32_t*)(sma + AVTL + off) =
                    packbf(v0 - __bfloat162float(h0), v1 - __bfloat162float(h1));
            }
        }
        if (tid < 192) {
            int gidx = s0 - t0 + 896 + tid;
            gidx = gidx < 0 ? 0 : (gidx > 2046 ? 2046 : gidx);
            Ws[tid] = TAB[h*2048 + gidx];
        }
        __syncthreads();

        float acc_s[8][4];
#pragma unroll
        for (int i = 0; i < 8; i++)
#pragma unroll
            for (int q = 0; q < 4; q++) acc_s[i][q] = 0.f;
        int qr = wid * 16 + (lane & 15);
#pragma unroll
        for (int ks = 0; ks < 4; ks++) {
            int chunk = ks * 2 + (lane >> 4);
            uint32_t qa[4], kh[4][4], kl[4][4];
            ldsm4(qa[0], qa[1], qa[2], qa[3], sb + AQHI + SWZ128(qr, chunk));
#pragma unroll
            for (int nt = 0; nt < 4; nt++) {
                int kr = nt * 16 + (lane & 15);
                ldsm4(kh[nt][0], kh[nt][1], kh[nt][2], kh[nt][3], sb + AKHI + SWZ128(kr, chunk));
                ldsm4(kl[nt][0], kl[nt][1], kl[nt][2], kl[nt][3], sb + AKLO + SWZ128(kr, chunk));
            }
#pragma unroll
            for (int nt8 = 0; nt8 < 8; nt8++) {
                int g = nt8 >> 1, s8 = nt8 & 1;
                mma16816(acc_s[nt8], qa, kh[g][s8], kh[g][s8 + 2]);
                mma16816(acc_s[nt8], qa, kl[g][s8], kl[g][s8 + 2]);
            }
            ldsm4(qa[0], qa[1], qa[2], qa[3], sb + AQLO + SWZ128(qr, chunk));
#pragma unroll
            for (int nt8 = 0; nt8 < 8; nt8++) {
                int g = nt8 >> 1, s8 = nt8 & 1;
                mma16816(acc_s[nt8], qa, kh[g][s8], kh[g][s8 + 2]);
            }
        }

#pragma unroll
        for (int h2 = 0; h2 < 2; h2++) {
            int rl = rloc0 + h2 * 8;
            float fv = h2 ? f1 : f0;
            float vmax = -1e30f;
#pragma unroll
            for (int nt = 0; nt < 8; nt++)
#pragma unroll
                for (int q = 0; q < 2; q++) {
                    int c = nt * 8 + cbase + q;
                    float sv = acc_s[nt][h2*2 + q] * 0.125f + fv * Ws[c - rl + 127];
                    acc_s[nt][h2*2 + q] = sv;
                    vmax = fmaxf(vmax, sv);
                }
            vmax = fmaxf(vmax, __shfl_xor_sync(0xffffffff, vmax, 1));
            vmax = fmaxf(vmax, __shfl_xor_sync(0xffffffff, vmax, 2));
            float mn = fmaxf(m_run[h2], vmax);
            float alpha = __expf(m_run[h2] - mn);
            m_run[h2] = mn;
            float rs = 0.f;
#pragma unroll
            for (int nt = 0; nt < 8; nt++)
#pragma unroll
                for (int q = 0; q < 2; q++) {
                    float p = __expf(acc_s[nt][h2*2 + q] - mn);
                    acc_s[nt][h2*2 + q] = p;
                    rs += p;
                }
            rs += __shfl_xor_sync(0xffffffff, rs, 1);
            rs += __shfl_xor_sync(0xffffffff, rs, 2);
            l_run[h2] = l_run[h2] * alpha + rs;
#pragma unroll
            for (int nt8 = 0; nt8 < 8; nt8++) {
                acc_o[nt8][h2*2 + 0] *= alpha;
                acc_o[nt8][h2*2 + 1] *= alpha;
            }
        }

#pragma unroll
        for (int kg = 0; kg < 4; kg++) {
            uint32_t ph[4], pl[4];
#pragma unroll
            for (int part = 0; part < 4; part++) {
                int tile = 2 * kg + (part >> 1);
                int o0 = (part & 1) * 2;
                float v0 = acc_s[tile][o0], v1 = acc_s[tile][o0 + 1];
                bf16 b0 = __float2bfloat16(v0), b1 = __float2bfloat16(v1);
                ph[part] = packbf(v0, v1);
                pl[part] = packbf(v0 - __bfloat162float(b0), v1 - __bfloat162float(b1));
            }
            int chunk = kg * 2 + (lane >> 4);
            uint32_t vh[4][4], vl[4][4];
#pragma unroll
            for (int ndt = 0; ndt < 4; ndt++) {
                int vr = ndt * 16 + (lane & 15);
                ldsm4(vh[ndt][0], vh[ndt][1], vh[ndt][2], vh[ndt][3], sb + AVTH + SWZ128(vr, chunk));
                ldsm4(vl[ndt][0], vl[ndt][1], vl[ndt][2], vl[ndt][3], sb + AVTL + SWZ128(vr, chunk));
            }
#pragma unroll
            for (int nd8 = 0; nd8 < 8; nd8++) {
                int g = nd8 >> 1, s8 = nd8 & 1;
                mma16816(acc_o[nd8], ph, vh[g][s8], vh[g][s8 + 2]);
                mma16816(acc_o[nd8], ph, vl[g][s8], vl[g][s8 + 2]);
                mma16816(acc_o[nd8], pl, vh[g][s8], vh[g][s8 + 2]);
            }
        }
    }

#pragma unroll
    for (int h2 = 0; h2 < 2; h2++) {
        float inv = 1.f / l_run[h2];
        int rg = t0 + rloc0 + h2 * 8;
#pragma unroll
        for (int nt8 = 0; nt8 < 8; nt8++) {
            int c = nt8 * 8 + cbase;
            float v0 = acc_o[nt8][h2*2 + 0] * inv;
            float v1 = acc_o[nt8][h2*2 + 1] * inv;
            size_t off = ((size_t)(b*T_ + rg))*DIM_ + h*64 + c;
            bf16_split2(v0, v1, Ohi, Olo, off);
        }
    }
}

// ---------------- GroupNorm finalize + apply ------------------------------------
__global__ void gn_finalize(int n) {
    int b = blockIdx.x;
    __shared__ double s1[128], s2[128];
    if (threadIdx.x < n) {
        s1[threadIdx.x] = g_PART[(b*128 + threadIdx.x)*2 + 0];
        s2[threadIdx.x] = g_PART[(b*128 + threadIdx.x)*2 + 1];
    }
    __syncthreads();
    if (threadIdx.x == 0) {
        double su = 0.0, sq = 0.0;
        for (int i = 0; i < n; i++) { su += s1[i]; sq += s2[i]; }
        double mean = su / (double)(T_*DIM_);
        double var = sq / (double)(T_*DIM_) - mean*mean;
        float inv = (float)(1.0 / sqrt(var + 1e-5));
        g_STATS[b] = make_float2((float)mean, inv);
    }
}
template<bool SILU>
__global__ void gn_apply(const float* __restrict__ x, const float* __restrict__ g,
                         const float* __restrict__ bt,
                         bf16* __restrict__ ohi, bf16* __restrict__ olo) {
    int idx = (blockIdx.x * 256 + threadIdx.x) * 4;
    int b = idx >> 19;
    int d = idx & (DIM_-1);
    float2 st = g_STATS[b];
    float4 xv = *(const float4*)(x + idx);
    float v0 = (xv.x - st.x) * st.y * g[d]     + bt[d];
    float v1 = (xv.y - st.x) * st.y * g[d + 1] + bt[d + 1];
    float v2 = (xv.z - st.x) * st.y * g[d + 2] + bt[d + 2];
    float v3 = (xv.w - st.x) * st.y * g[d + 3] + bt[d + 3];
    if (SILU) {
        v0 = v0 / (1.f + expf(-v0));
        v1 = v1 / (1.f + expf(-v1));
        v2 = v2 / (1.f + expf(-v2));
        v3 = v3 / (1.f + expf(-v3));
    }
    bf16_split2(v0, v1, ohi, olo, idx);
    bf16_split2(v2, v3, ohi, olo, idx + 2);
}

// ---------------- depthwise conv (GLU pre-applied) + GN partials ----------------
__global__ void __launch_bounds__(256) dwconv_red(
    const float* __restrict__ gluin, const float* __restrict__ w,
    const float* __restrict__ wb, float* __restrict__ out)
{
    __shared__ float smv[94][64];
    __shared__ float smw[64][33];
    __shared__ double rsum[256], rsq[256];
    int b = blockIdx.z, t0 = blockIdx.x * 64, d0 = blockIdx.y * 64;
    int tid = threadIdx.x;
    for (int i = tid; i < 64 * KW; i += 256) {
        int dd = i / KW, j = i - dd * KW;
        smw[dd][j] = w[(size_t)(d0 + dd) * KW + j];
    }
    for (int i = tid; i < 94 * 64; i += 256) {
        int r = i >> 6, d = i & 63;
        int tt = t0 - 15 + r;
        float v = 0.f;
        if (tt >= 0 && tt < T_)
            v = gluin[((size_t)(b*T_ + tt))*DIM_ + d0 + d];
        smv[r][d] = v;
    }
    __syncthreads();
    int d = tid & 63, tr = tid >> 6;
    float wr[KW];
#pragma unroll
    for (int j = 0; j < KW; j++) wr[j] = smw[d][j];
    float bias = wb[d0 + d];
    double su = 0.0, sq = 0.0;
#pragma unroll 4
    for (int i = 0; i < 16; i++) {
        int t = tr * 16 + i;
        float acc = bias;
#pragma unroll
        for (int j = 0; j < KW; j++) acc += wr[j] * smv[t + j][d];
        out[((size_t)(b*T_ + t0 + t))*DIM_ + d0 + d] = acc;
        su += acc; sq += (double)acc * acc;
    }
    rsum[tid] = su; rsq[tid] = sq;
    __syncthreads();
    for (int st = 128; st > 0; st >>= 1) {
        if (tid < st) { rsum[tid] += rsum[tid + st]; rsq[tid] += rsq[tid + st]; }
        __syncthreads();
    }
    if (tid == 0) {
        int tidx = blockIdx.x * 8 + blockIdx.y;
        g_PART[(b*128 + tidx)*2 + 0] = rsum[0];
        g_PART[(b*128 + tidx)*2 + 1] = rsq[0];
    }
}

// ---------------- host ----------------------------------------------------------
static float* sym_f(const void* s) { void* p = nullptr; cudaGetSymbolAddress(&p, s); return (float*)p; }
static bf16* sym_b(const void* s) { void* p = nullptr; cudaGetSymbolAddress(&p, s); return (bf16*)p; }

#define SMEM_128 (512 + 3*(2*128*64 + 2*8192))
#define SMEM_64  (512 + 3*(2*64*64  + 2*8192))

extern "C" void kernel_launch(void* const* d_in, const int* in_sizes, int n_in,
                              void* d_out, int out_size) {
    const float* x      = (const float*)d_in[0];
    const float* ff1_w1 = (const float*)d_in[1];
    const float* ff1_b1 = (const float*)d_in[2];
    const float* ff1_w2 = (const float*)d_in[3];
    const float* ff1_b2 = (const float*)d_in[4];
    const float* qkv_w  = (const float*)d_in[5];
    const float* qkv_b  = (const float*)d_in[6];
    const float* out_w  = (const float*)d_in[7];
    const float* out_b  = (const float*)d_in[8];
    const float* gn1_g  = (const float*)d_in[9];
    const float* gn1_b  = (const float*)d_in[10];
    const float* pw1_w  = (const float*)d_in[11];
    const float* pw1_b  = (const float*)d_in[12];
    const float* dw_w   = (const float*)d_in[13];
    const float* dw_b   = (const float*)d_in[14];
    const float* gn2_g  = (const float*)d_in[15];
    const float* gn2_b  = (const float*)d_in[16];
    const float* pw2_w  = (const float*)d_in[17];
    const float* pw2_b  = (const float*)d_in[18];
    const float* ff2_w1 = (const float*)d_in[19];
    const float* ff2_b1 = (const float*)d_in[20];
    const float* ff2_w2 = (const float*)d_in[21];
    const float* ff2_b2 = (const float*)d_in[22];
    const float* rel_embed = (const float*)d_in[23];
    const float* gate_u = (const float*)d_in[24];
    const float* gate_w = (const float*)d_in[25];
    const float* scale_h = (const float*)d_in[26];

    float* S   = sym_f(g_S);
    float* T1  = sym_f(g_T1);
    float* QKV = sym_f(g_QKV);
    float* C1  = sym_f(g_C1);
    float* F   = sym_f(g_F);
    float* TAB = sym_f(g_TAB);
    bf16 *Shi = sym_b(g_Shi),  *Slo = sym_b(g_Slo);
    bf16 *Thi = sym_b(g_T1hi), *Tlo = sym_b(g_T1lo);
    bf16 *Ohi = sym_b(g_Ohi),  *Olo = sym_b(g_Olo);
    bf16 *Nhi = sym_b(g_N1hi), *Nlo = sym_b(g_N1lo);
    bf16 *Wf1a_hi = sym_b(g_Wf1a_hi), *Wf1a_lo = sym_b(g_Wf1a_lo);
    bf16 *Wf1b_hi = sym_b(g_Wf1b_hi), *Wf1b_lo = sym_b(g_Wf1b_lo);
    bf16 *Wqkv_hi = sym_b(g_Wqkv_hi), *Wqkv_lo = sym_b(g_Wqkv_lo);
    bf16 *Wout_hi = sym_b(g_Wout_hi), *Wout_lo = sym_b(g_Wout_lo);
    bf16 *Wpw1_hi = sym_b(g_Wpw1_hi), *Wpw1_lo = sym_b(g_Wpw1_lo);
    bf16 *Wpw2_hi = sym_b(g_Wpw2_hi), *Wpw2_lo = sym_b(g_Wpw2_lo);
    bf16 *Wf2a_hi = sym_b(g_Wf2a_hi), *Wf2a_lo = sym_b(g_Wf2a_lo);
    bf16 *Wf2b_hi = sym_b(g_Wf2b_hi), *Wf2b_lo = sym_b(g_Wf2b_lo);

    const int M = B_*T_;

    cudaFuncSetAttribute(gemm_mma<128,false,false,false,false>, cudaFuncAttributeMaxDynamicSharedMemorySize, SMEM_128);
    cudaFuncSetAttribute(gemm_mma<128,true,false,false,false>,  cudaFuncAttributeMaxDynamicSharedMemorySize, SMEM_128);
    cudaFuncSetAttribute(gemm_mma<128,false,false,false,true>,  cudaFuncAttributeMaxDynamicSharedMemorySize, SMEM_128);
    cudaFuncSetAttribute(gemm_mma<64,false,false,false,false>,  cudaFuncAttributeMaxDynamicSharedMemorySize, SMEM_64);
    cudaFuncSetAttribute(gemm_mma<64,false,true,false,false>,   cudaFuncAttributeMaxDynamicSharedMemorySize, SMEM_64);
    cudaFuncSetAttribute(gemm_mma<64,false,false,true,false>,   cudaFuncAttributeMaxDynamicSharedMemorySize, SMEM_64);
    cudaFuncSetAttribute(attn_mma, cudaFuncAttributeMaxDynamicSharedMemorySize, ATTN_SMEM);

    // prep: all weight splits + rel table + input transpose in one launch
    prep_all<<<8000, 256>>>(ff1_w1, ff1_w2, qkv_w, out_w, pw1_w, pw2_w, ff2_w1, ff2_w2,
                            rel_embed, x, S, Shi, Slo);

    gemm_mma<128,true,false,false,false><<<dim3(FF_/128, M/128), 256, SMEM_128>>>(Shi, Slo, Wf1a_hi, Wf1a_lo, ff1_b1, nullptr, nullptr, Thi, Tlo, M, FF_, DIM_, 1.0f);
    gemm_mma<64,false,false,false,false><<<dim3(DIM_/128, M/64), 256, SMEM_64>>>(Thi, Tlo, Wf1b_hi, Wf1b_lo, ff1_b2, S, S, Shi, Slo, M, DIM_, FF_, 0.5f);
    gemm_mma<128,false,false,false,false><<<dim3(1536/128, M/128), 256, SMEM_128>>>(Shi, Slo, Wqkv_hi, Wqkv_lo, qkv_b, nullptr, QKV, nullptr, nullptr, M, 1536, DIM_, 1.0f);

    gates_kernel<<<(B_*H_*T_)/8, 256>>>(QKV, gate_u, gate_w, scale_h, F);
    attn_mma<<<dim3(T_/128, H_, B_), 256, ATTN_SMEM>>>(QKV, F, TAB, Ohi, Olo);

    // out proj + residual; fused GN1 partials
    gemm_mma<64,false,true,false,false><<<dim3(DIM_/128, M/64), 256, SMEM_64>>>(Ohi, Olo, Wout_hi, Wout_lo, out_b, S, S, nullptr, nullptr, M, DIM_, DIM_, 1.0f);

    gn_finalize<<<B_, 64>>>(64);
    gn_apply<false><<<(B_*T_*DIM_)/1024, 256>>>(S, gn1_g, gn1_b, Nhi, Nlo);

    // pw1 (interleaved weights) + GLU epilogue -> C1
    gemm_mma<128,false,false,false,true><<<dim3(1024/128, M/128), 256, SMEM_128>>>(Nhi, Nlo, Wpw1_hi, Wpw1_lo, pw1_b, nullptr, C1, nullptr, nullptr, M, 1024, DIM_, 1.0f);

    // depthwise conv + GN2 partials -> T1
    dwconv_red<<<dim3(T_/64, DIM_/64, B_), 256>>>(C1, dw_w, dw_b, T1);

    gn_finalize<<<B_, 128>>>(128);
    gn_apply<true><<<(B_*T_*DIM_)/1024, 256>>>(T1, gn2_g, gn2_b, Nhi, Nlo);

    gemm_mma<64,false,false,false,false><<<dim3(DIM_/128, M/64), 256, SMEM_64>>>(Nhi, Nlo, Wpw2_hi, Wpw2_lo, pw2_b, S, S, Shi, Slo, M, DIM_, DIM_, 1.0f);

    gemm_mma<128,true,false,false,false><<<dim3(FF_/128, M/128), 256, SMEM_128>>>(Shi, Slo, Wf2a_hi, Wf2a_lo, ff2_b1, nullptr, nullptr, Thi, Tlo, M, FF_, DIM_, 1.0f);
    // FF2b: direct transposed output
    gemm_mma<64,false,false,true,false><<<dim3(DIM_/128, M/64), 256, SMEM_64>>>(Thi, Tlo, Wf2b_hi, Wf2b_lo, ff2_b2, S, (float*)d_out, nullptr, nullptr, M, DIM_, FF_, 0.5f);
}